// round 2
// baseline (speedup 1.0000x reference)
#include <cuda_runtime.h>
#include <math.h>

// Problem constants (B=128 trees, depth D=6, NPT=127)
#define Hh     450
#define NNODE  16256   // 128*127
#define NEDGE  32256   // 2*128*126

typedef unsigned long long ull;

// Scratch (static device globals; allocation-free kernel_launch)
__device__ float g_x  [NNODE*Hh];
__device__ float g_Xz [NNODE*Hh];
__device__ float g_Xh [NNODE*Hh];
__device__ float g_Xr [NNODE*Hh];
__device__ float g_Xg [NNODE*Hh];
__device__ float g_m  [NEDGE*Hh];
__device__ float g_rm [NEDGE*Hh];
__device__ float g_nm [NNODE*Hh];
__device__ float g_nrm[NNODE*Hh];

__device__ __forceinline__ float sigmoidf_(float v){ return 1.0f/(1.0f+expf(-v)); }

// packed f32x2 helpers (Blackwell FFMA2 — only reachable via PTX)
__device__ __forceinline__ ull pk2(float x){
  ull r; asm("mov.b64 %0,{%1,%1};" : "=l"(r) : "f"(x)); return r;
}
__device__ __forceinline__ void fma2(ull &d, ull a, ull b){
  asm("fma.rn.f32x2 %0,%1,%2,%0;" : "+l"(d) : "l"(a), "l"(b));
}
__device__ __forceinline__ float2 up2(ull v){
  float2 r; asm("mov.b64 {%0,%1},%2;" : "=f"(r.x), "=f"(r.y) : "l"(v)); return r;
}

// ---------------------------------------------------------------------------
// init: gather embeddings (float2), zero node accumulators
// ---------------------------------------------------------------------------
__global__ void k_init(const int* __restrict__ wid, const float* __restrict__ emb){
  const int H2 = Hh/2;
  int i2 = blockIdx.x*blockDim.x + threadIdx.x;
  if (i2 < NNODE*H2){
    int r = i2 / H2, c = (i2 - r*H2)*2;
    float2 v = *(const float2*)(emb + (size_t)wid[r]*Hh + c);
    *(float2*)(g_x  + (size_t)r*Hh + c) = v;
    *(float2*)(g_nm + (size_t)r*Hh + c) = make_float2(0.f,0.f);
    *(float2*)(g_nrm+ (size_t)r*Hh + c) = make_float2(0.f,0.f);
  }
}

// ---------------------------------------------------------------------------
// Precompute GEMM: C(which) = g_x @ B + bias   (M=NNODE, N=K=450)
// 64x128 tile, 4x8 microtile, FFMA2
// ---------------------------------------------------------------------------
__global__ __launch_bounds__(256) void k_gemm_bias(
    const float* __restrict__ B, const float* __restrict__ bias, int which){
  constexpr int BM=64, BN=128, BK=16;
  __shared__ float As[BM][BK+1];
  __shared__ float Bs[BK][BN];
  float* C = (which==0)?g_Xz:(which==1)?g_Xh:(which==2)?g_Xr:g_Xg;
  int bm = blockIdx.x*BM, bn = blockIdx.y*BN;
  int tid = threadIdx.x, ty = tid>>4, tx = tid&15;
  ull acc[4][4] = {};
  int lr = tid>>2, lk = (tid&3)*4;
  const float* Ar = g_x + (size_t)(bm+lr)*Hh;
  int kr = tid>>4, nc = (tid&15)*8;

  for (int k0=0; k0<Hh; k0+=BK){
    #pragma unroll
    for (int u=0;u<4;u+=2){
      int gk = k0 + lk + u;
      float2 v = (gk<Hh)? *(const float2*)(Ar+gk) : make_float2(0.f,0.f);
      As[lr][lk+u] = v.x; As[lr][lk+u+1] = v.y;
    }
    {
      int gk = k0 + kr;
      const float* Brow = B + (size_t)gk*Hh;
      #pragma unroll
      for (int u=0;u<8;u+=2){
        int gn = bn + nc + u;
        float2 v = (gk<Hh && gn<Hh)? *(const float2*)(Brow+gn) : make_float2(0.f,0.f);
        Bs[kr][nc+u] = v.x; Bs[kr][nc+u+1] = v.y;
      }
    }
    __syncthreads();
    #pragma unroll
    for (int kk=0; kk<BK; kk++){
      ull av[4];
      #pragma unroll
      for (int i=0;i<4;i++) av[i] = pk2(As[ty*4+i][kk]);
      const ull* bp = (const ull*)&Bs[kk][tx*8];
      ull b0=bp[0], b1=bp[1], b2=bp[2], b3=bp[3];
      #pragma unroll
      for (int i=0;i<4;i++){
        fma2(acc[i][0],av[i],b0); fma2(acc[i][1],av[i],b1);
        fma2(acc[i][2],av[i],b2); fma2(acc[i][3],av[i],b3);
      }
    }
    __syncthreads();
  }
  #pragma unroll
  for (int i=0;i<4;i++){
    int r = bm + ty*4 + i;
    #pragma unroll
    for (int q=0;q<4;q++){
      int c = bn + tx*8 + 2*q;
      if (c >= Hh) continue;
      float2 a = up2(acc[i][q]);
      float2 bv = *(const float2*)(bias + c);
      *(float2*)(C + (size_t)r*Hh + c) = make_float2(a.x+bv.x, a.y+bv.y);
    }
  }
}

// ---------------------------------------------------------------------------
// Level 0 (deepest leaves): s = arm = 0 -> m_new = sigmoid(Xz[se])*tanh(Xh[se])
// ---------------------------------------------------------------------------
__global__ void k_lvl0(const int* __restrict__ sched, const int* __restrict__ srcv){
  int e  = sched[blockIdx.x];
  int se = srcv[e];
  const float* xz = g_Xz + (size_t)se*Hh;
  const float* xh = g_Xh + (size_t)se*Hh;
  float* mo = g_m + (size_t)e*Hh;
  int c = threadIdx.x*2;
  if (c < Hh){
    float2 a = *(const float2*)(xz+c), b = *(const float2*)(xh+c);
    *(float2*)(mo+c) = make_float2(sigmoidf_(a.x)*tanhf(b.x),
                                   sigmoidf_(a.y)*tanhf(b.y));
  }
}

// ---------------------------------------------------------------------------
// GEMM A (dual): Z = S @ WzB, MT = ARM @ WhB, fused gather + GRU epilogue.
// ---------------------------------------------------------------------------
template<int BM,int BN,int TM,int TN>
__global__ __launch_bounds__(256) void k_gemmA(
    const int* __restrict__ sched, const int* __restrict__ srcv,
    const int* __restrict__ revv,
    const float* __restrict__ WzB, const float* __restrict__ WhB, int sub){
  constexpr int BK=16;
  constexpr int TPR = 256/BM;      // threads per A row
  constexpr int AEL = BK/TPR;      // k-floats per thread
  constexpr int BEL = BN/16;       // B cols per thread
  constexpr int NQ  = TN/2;
  __shared__ float Ss[BM][BK+1], Rs[BM][BK+1];
  __shared__ float Bz[BK][BN], Bh[BK][BN];
  __shared__ int s_eid[BM], s_se[BM], s_rv[BM];
  int bm = blockIdx.x*BM, bn = blockIdx.y*BN;
  int tid = threadIdx.x;
  if (tid < BM){
    int e = sched[bm + tid];
    s_eid[tid] = e; s_se[tid] = srcv[e]; s_rv[tid] = revv[e];
  }
  __syncthreads();
  int ty = tid>>4, tx = tid&15;
  ull accZ[TM][NQ] = {}, accH[TM][NQ] = {};
  int lr = tid/TPR, lk = (tid%TPR)*AEL;
  const float* nmr = g_nm  + (size_t)s_se[lr]*Hh;
  const float* nrr = g_nrm + (size_t)s_se[lr]*Hh;
  const float* mr  = g_m   + (size_t)s_rv[lr]*Hh;
  const float* rmr = g_rm  + (size_t)s_rv[lr]*Hh;
  int kr = tid>>4, nc = (tid&15)*BEL;

  for (int k0=0; k0<Hh; k0+=BK){
    #pragma unroll
    for (int u=0;u<AEL;u+=2){
      int gk = k0 + lk + u;
      float2 vm = make_float2(0.f,0.f), vr = make_float2(0.f,0.f);
      if (gk < Hh){
        vm = *(const float2*)(nmr+gk);
        vr = *(const float2*)(nrr+gk);
        if (sub){
          float2 a = *(const float2*)(mr+gk), b = *(const float2*)(rmr+gk);
          vm.x -= a.x; vm.y -= a.y; vr.x -= b.x; vr.y -= b.y;
        }
      }
      Ss[lr][lk+u] = vm.x; Ss[lr][lk+u+1] = vm.y;
      Rs[lr][lk+u] = vr.x; Rs[lr][lk+u+1] = vr.y;
    }
    {
      int gk = k0 + kr;
      const float* zr = WzB + (size_t)gk*Hh;
      const float* hr = WhB + (size_t)gk*Hh;
      #pragma unroll
      for (int u=0;u<BEL;u+=2){
        int gn = bn + nc + u;
        bool ok = (gk<Hh) && (gn<Hh);
        float2 vz = ok? *(const float2*)(zr+gn) : make_float2(0.f,0.f);
        float2 vh = ok? *(const float2*)(hr+gn) : make_float2(0.f,0.f);
        Bz[kr][nc+u] = vz.x; Bz[kr][nc+u+1] = vz.y;
        Bh[kr][nc+u] = vh.x; Bh[kr][nc+u+1] = vh.y;
      }
    }
    __syncthreads();
    #pragma unroll
    for (int kk=0; kk<BK; kk++){
      ull av[TM], aw[TM];
      #pragma unroll
      for (int i=0;i<TM;i++){ av[i]=pk2(Ss[ty*TM+i][kk]); aw[i]=pk2(Rs[ty*TM+i][kk]); }
      const ull* pz = (const ull*)&Bz[kk][tx*TN];
      const ull* ph = (const ull*)&Bh[kk][tx*TN];
      #pragma unroll
      for (int q=0;q<NQ;q++){
        ull bz=pz[q], bh2=ph[q];
        #pragma unroll
        for (int i=0;i<TM;i++){ fma2(accZ[i][q],av[i],bz); fma2(accH[i][q],aw[i],bh2); }
      }
    }
    __syncthreads();
  }
  #pragma unroll
  for (int i=0;i<TM;i++){
    int r = ty*TM + i;
    int se = s_se[r], e = s_eid[r], rv = s_rv[r];
    const float* xz = g_Xz + (size_t)se*Hh;
    const float* xh = g_Xh + (size_t)se*Hh;
    const float* nm = g_nm + (size_t)se*Hh;
    const float* mrr= g_m  + (size_t)rv*Hh;
    float* mo = g_m + (size_t)e*Hh;
    #pragma unroll
    for (int q=0;q<NQ;q++){
      int c = bn + tx*TN + 2*q;
      if (c >= Hh) continue;
      float2 za = up2(accZ[i][q]), ha = up2(accH[i][q]);
      float2 xzv = *(const float2*)(xz+c), xhv = *(const float2*)(xh+c);
      float2 nmv = *(const float2*)(nm+c);
      float2 mv  = sub ? *(const float2*)(mrr+c) : make_float2(0.f,0.f);
      float z0 = sigmoidf_(za.x + xzv.x), mt0 = tanhf(ha.x + xhv.x);
      float z1 = sigmoidf_(za.y + xzv.y), mt1 = tanhf(ha.y + xhv.y);
      float s0 = nmv.x - mv.x, s1 = nmv.y - mv.y;
      *(float2*)(mo+c) = make_float2((1.f-z0)*s0 + z0*mt0,
                                     (1.f-z1)*s1 + z1*mt1);
    }
  }
}

// ---------------------------------------------------------------------------
// GEMM B: R = m_new @ Ur; epilogue r=sigmoid(R+Xr[dst]); rm=r*m_new;
// deterministic non-atomic scatter into node_m/node_rm (sibling pairs on up).
// ---------------------------------------------------------------------------
template<int BM,int BN,int TM,int TN>
__global__ __launch_bounds__(256) void k_gemmB(
    const int* __restrict__ sched, const int* __restrict__ dstv,
    const float* __restrict__ Ur, int up){
  constexpr int BK=16;
  constexpr int TPR = 256/BM;
  constexpr int AEL = BK/TPR;
  constexpr int BEL = BN/16;
  constexpr int NQ  = TN/2;
  __shared__ float As[BM][BK+1];
  __shared__ float Bs[BK][BN];
  __shared__ int s_eid[BM], s_de[BM];
  int bm = blockIdx.x*BM, bn = blockIdx.y*BN;
  int tid = threadIdx.x;
  if (tid < BM){
    int e = sched[bm + tid];
    s_eid[tid] = e; s_de[tid] = dstv[e];
  }
  __syncthreads();
  int ty = tid>>4, tx = tid&15;
  ull acc[TM][NQ] = {};
  int lr = tid/TPR, lk = (tid%TPR)*AEL;
  const float* Ar = g_m + (size_t)s_eid[lr]*Hh;
  int kr = tid>>4, nc = (tid&15)*BEL;

  for (int k0=0; k0<Hh; k0+=BK){
    #pragma unroll
    for (int u=0;u<AEL;u+=2){
      int gk = k0 + lk + u;
      float2 v = (gk<Hh)? *(const float2*)(Ar+gk) : make_float2(0.f,0.f);
      As[lr][lk+u] = v.x; As[lr][lk+u+1] = v.y;
    }
    {
      int gk = k0 + kr;
      const float* br = Ur + (size_t)gk*Hh;
      #pragma unroll
      for (int u=0;u<BEL;u+=2){
        int gn = bn + nc + u;
        float2 v = ((gk<Hh)&&(gn<Hh))? *(const float2*)(br+gn) : make_float2(0.f,0.f);
        Bs[kr][nc+u] = v.x; Bs[kr][nc+u+1] = v.y;
      }
    }
    __syncthreads();
    #pragma unroll
    for (int kk=0; kk<BK; kk++){
      ull av[TM];
      #pragma unroll
      for (int i=0;i<TM;i++) av[i] = pk2(As[ty*TM+i][kk]);
      const ull* bp = (const ull*)&Bs[kk][tx*TN];
      #pragma unroll
      for (int q=0;q<NQ;q++){
        ull b = bp[q];
        #pragma unroll
        for (int i=0;i<TM;i++) fma2(acc[i][q], av[i], b);
      }
    }
    __syncthreads();
  }
  #pragma unroll
  for (int q=0;q<NQ;q++){
    int c = bn + tx*TN + 2*q;
    if (c >= Hh) continue;
    float2 mv[TM], rmv[TM];
    #pragma unroll
    for (int i=0;i<TM;i++){
      int r = ty*TM + i;
      int e = s_eid[r], de = s_de[r];
      mv[i] = *(const float2*)(g_m + (size_t)e*Hh + c);
      float2 xr = *(const float2*)(g_Xr + (size_t)de*Hh + c);
      float2 a = up2(acc[i][q]);
      rmv[i] = make_float2(sigmoidf_(a.x+xr.x)*mv[i].x,
                           sigmoidf_(a.y+xr.y)*mv[i].y);
      *(float2*)(g_rm + (size_t)e*Hh + c) = rmv[i];
    }
    if (up){
      #pragma unroll
      for (int i=0;i<TM;i+=2){
        int de = s_de[ty*TM + i];          // sibling pair shares dst
        size_t idx = (size_t)de*Hh + c;
        float2 nm = *(float2*)(g_nm+idx), nr = *(float2*)(g_nrm+idx);
        nm.x += mv[i].x + mv[i+1].x;  nm.y += mv[i].y + mv[i+1].y;
        nr.x += rmv[i].x + rmv[i+1].x; nr.y += rmv[i].y + rmv[i+1].y;
        *(float2*)(g_nm+idx) = nm; *(float2*)(g_nrm+idx) = nr;
      }
    } else {
      #pragma unroll
      for (int i=0;i<TM;i++){
        int de = s_de[ty*TM + i];
        size_t idx = (size_t)de*Hh + c;
        float2 nm = *(float2*)(g_nm+idx), nr = *(float2*)(g_nrm+idx);
        nm.x += mv[i].x;  nm.y += mv[i].y;
        nr.x += rmv[i].x; nr.y += rmv[i].y;
        *(float2*)(g_nm+idx) = nm; *(float2*)(g_nrm+idx) = nr;
      }
    }
  }
}

// ---------------------------------------------------------------------------
// Final readout: out = relu(Xg + node_m @ WgB)
// ---------------------------------------------------------------------------
__global__ __launch_bounds__(256) void k_final(
    const float* __restrict__ WgB, float* __restrict__ out){
  constexpr int BM=64, BN=128, BK=16;
  __shared__ float As[BM][BK+1];
  __shared__ float Bs[BK][BN];
  int bm = blockIdx.x*BM, bn = blockIdx.y*BN;
  int tid = threadIdx.x, ty = tid>>4, tx = tid&15;
  ull acc[4][4] = {};
  int lr = tid>>2, lk = (tid&3)*4;
  const float* Ar = g_nm + (size_t)(bm+lr)*Hh;
  int kr = tid>>4, nc = (tid&15)*8;

  for (int k0=0; k0<Hh; k0+=BK){
    #pragma unroll
    for (int u=0;u<4;u+=2){
      int gk = k0 + lk + u;
      float2 v = (gk<Hh)? *(const float2*)(Ar+gk) : make_float2(0.f,0.f);
      As[lr][lk+u] = v.x; As[lr][lk+u+1] = v.y;
    }
    {
      int gk = k0 + kr;
      const float* Brow = WgB + (size_t)gk*Hh;
      #pragma unroll
      for (int u=0;u<8;u+=2){
        int gn = bn + nc + u;
        float2 v = (gk<Hh && gn<Hh)? *(const float2*)(Brow+gn) : make_float2(0.f,0.f);
        Bs[kr][nc+u] = v.x; Bs[kr][nc+u+1] = v.y;
      }
    }
    __syncthreads();
    #pragma unroll
    for (int kk=0; kk<BK; kk++){
      ull av[4];
      #pragma unroll
      for (int i=0;i<4;i++) av[i] = pk2(As[ty*4+i][kk]);
      const ull* bp = (const ull*)&Bs[kk][tx*8];
      ull b0=bp[0], b1=bp[1], b2=bp[2], b3=bp[3];
      #pragma unroll
      for (int i=0;i<4;i++){
        fma2(acc[i][0],av[i],b0); fma2(acc[i][1],av[i],b1);
        fma2(acc[i][2],av[i],b2); fma2(acc[i][3],av[i],b3);
      }
    }
    __syncthreads();
  }
  #pragma unroll
  for (int i=0;i<4;i++){
    int r = bm + ty*4 + i;
    const float* xg = g_Xg + (size_t)r*Hh;
    #pragma unroll
    for (int q=0;q<4;q++){
      int c = bn + tx*8 + 2*q;
      if (c >= Hh) continue;
      float2 a = up2(acc[i][q]);
      float2 xv = *(const float2*)(xg+c);
      *(float2*)(out + (size_t)r*Hh + c) =
          make_float2(fmaxf(a.x+xv.x,0.f), fmaxf(a.y+xv.y,0.f));
    }
  }
}

// ---------------------------------------------------------------------------
// kernel_launch
// Inputs: 0 wid, 1 src, 2 dst, 3 rev, 4 sched, 5 emb, 6 Wz, 7 bz,
//         8 Wr, 9 Ur, 10 bur, 11 Wh, 12 bh, 13 Wg, 14 bg
// ---------------------------------------------------------------------------
extern "C" void kernel_launch(void* const* d_in, const int* in_sizes, int n_in,
                              void* d_out, int out_size) {
  const int*   wid   = (const int*)  d_in[0];
  const int*   srcv  = (const int*)  d_in[1];
  const int*   dstv  = (const int*)  d_in[2];
  const int*   revv  = (const int*)  d_in[3];
  const int*   sched = (const int*)  d_in[4];
  const float* emb   = (const float*)d_in[5];
  const float* Wz    = (const float*)d_in[6];
  const float* bz    = (const float*)d_in[7];
  const float* Wr    = (const float*)d_in[8];
  const float* Ur    = (const float*)d_in[9];
  const float* bur   = (const float*)d_in[10];
  const float* Wh    = (const float*)d_in[11];
  const float* bh    = (const float*)d_in[12];
  const float* Wg    = (const float*)d_in[13];
  const float* bg    = (const float*)d_in[14];
  float* out = (float*)d_out;

  const int lmax = in_sizes[4] / 12;   // 8192
  static const int NeTab[12] = {8192,4096,2048,1024,512,256,
                                 256,512,1024,2048,4096,8192};

  // init + precompute (hoisted x-GEMMs)
  k_init<<<(NNODE*(Hh/2) + 255)/256, 256>>>(wid, emb);
  dim3 gpre(NNODE/64, 4);
  k_gemm_bias<<<gpre, 256>>>(Wz, bz,  0);   // Xz = x@Wz_top + bz
  k_gemm_bias<<<gpre, 256>>>(Wh, bh,  1);   // Xh = x@Wh_top + bh
  k_gemm_bias<<<gpre, 256>>>(Wr, bur, 2);   // Xr = x@Wr     + bur
  k_gemm_bias<<<gpre, 256>>>(Wg, bg,  3);   // Xg = x@Wg_top + bg

  // level 0 (s = arm = 0): pointwise m_new, then R-GEMM + scatter
  k_lvl0<<<NeTab[0], 256>>>(sched, srcv);
  {
    dim3 g(NeTab[0]/64, 4);
    k_gemmB<64,128,4,8><<<g, 256>>>(sched, dstv, Ur, 1);
  }
  // levels 1..11
  for (int lvl = 1; lvl < 12; lvl++) {
    int Ne  = NeTab[lvl];
    int sub = (lvl >= 6) ? 1 : 0;
    int up  = (lvl <  6) ? 1 : 0;
    const int* sc = sched + lvl*lmax;
    if (Ne >= 2048){
      dim3 g(Ne/64, 4);
      k_gemmA<64,128,4,8><<<g, 256>>>(sc, srcv, revv, Wz + Hh*Hh, Wh + Hh*Hh, sub);
      k_gemmB<64,128,4,8><<<g, 256>>>(sc, dstv, Ur, up);
    } else {
      dim3 g(Ne/32, 15);
      k_gemmA<32,32,2,2><<<g, 256>>>(sc, srcv, revv, Wz + Hh*Hh, Wh + Hh*Hh, sub);
      k_gemmB<32,32,2,2><<<g, 256>>>(sc, dstv, Ur, up);
    }
  }

  // readout
  dim3 gf(NNODE/64, 4);
  k_final<<<gf, 256>>>(Wg + Hh*Hh, out);
}

// round 3
// speedup vs baseline: 1.2909x; 1.2909x over previous
#include <cuda_runtime.h>
#include <math.h>

// Problem constants (B=128 trees, depth D=6, NPT=127)
#define Hh     450
#define NNODE  16256   // 128*127
#define NEDGE  32256   // 2*128*126

// Scratch (static device globals; allocation-free kernel_launch)
__device__ float g_x  [NNODE*Hh];
__device__ float g_Xz [NNODE*Hh];
__device__ float g_Xh [NNODE*Hh];
__device__ float g_Xr [NNODE*Hh];
__device__ float g_Xg [NNODE*Hh];
__device__ float g_m  [NEDGE*Hh];
__device__ float g_rm [NEDGE*Hh];
__device__ float g_nm [NNODE*Hh];
__device__ float g_nrm[NNODE*Hh];

__device__ __forceinline__ float sigmoidf_(float v){ return 1.0f/(1.0f+expf(-v)); }

// ---------------------------------------------------------------------------
// init: gather embeddings (float2), zero node accumulators
// ---------------------------------------------------------------------------
__global__ void k_init(const int* __restrict__ wid, const float* __restrict__ emb){
  const int H2 = Hh/2;
  int i2 = blockIdx.x*blockDim.x + threadIdx.x;
  if (i2 < NNODE*H2){
    int r = i2 / H2, c = (i2 - r*H2)*2;
    float2 v = *(const float2*)(emb + (size_t)wid[r]*Hh + c);
    *(float2*)(g_x  + (size_t)r*Hh + c) = v;
    *(float2*)(g_nm + (size_t)r*Hh + c) = make_float2(0.f,0.f);
    *(float2*)(g_nrm+ (size_t)r*Hh + c) = make_float2(0.f,0.f);
  }
}

// ---------------------------------------------------------------------------
// Dense GEMM (128x128x8, 8x8 microtile):
//   csel 0..3:  C = g_x @ Bw + bias     (C = Xz/Xh/Xr/Xg)
//   csel 4:     out = relu(g_nm @ Bw + g_Xg)
// ---------------------------------------------------------------------------
__global__ __launch_bounds__(256) void k_gemmC(
    const float* __restrict__ Bw, const float* __restrict__ bias,
    int asel, int csel, float* __restrict__ outp){
  __shared__ float As[8][128];
  __shared__ float Bs[8][128];
  const float* A = asel ? g_nm : g_x;
  float* C = (csel==0)?g_Xz:(csel==1)?g_Xh:(csel==2)?g_Xr:(csel==3)?g_Xg:outp;
  int bm = blockIdx.x*128, bn = blockIdx.y*128;
  int tid = threadIdx.x, ty = tid>>4, tx = tid&15;
  float acc[8][8] = {};
  int lr = tid>>1, lk = (tid&1)*4;
  const float* Ar = A + (size_t)(bm+lr)*Hh;
  int kr = tid>>5, nc = (tid&31)*4;

  for (int k0=0; k0<Hh; k0+=8){
    #pragma unroll
    for (int u=0;u<4;u+=2){
      int gk = k0 + lk + u;
      float2 v = (gk<Hh)? *(const float2*)(Ar+gk) : make_float2(0.f,0.f);
      As[lk+u][lr] = v.x; As[lk+u+1][lr] = v.y;
    }
    {
      int gk = k0 + kr;
      const float* Br = Bw + (size_t)gk*Hh;
      #pragma unroll
      for (int u=0;u<4;u+=2){
        int gn = bn + nc + u;
        float2 v = (gk<Hh && gn<Hh)? *(const float2*)(Br+gn) : make_float2(0.f,0.f);
        Bs[kr][nc+u] = v.x; Bs[kr][nc+u+1] = v.y;
      }
    }
    __syncthreads();
    #pragma unroll
    for (int kk=0; kk<8; kk++){
      float4 a0 = *(const float4*)&As[kk][ty*8];
      float4 a1 = *(const float4*)&As[kk][ty*8+4];
      float4 b0 = *(const float4*)&Bs[kk][tx*8];
      float4 b1 = *(const float4*)&Bs[kk][tx*8+4];
      float a[8] = {a0.x,a0.y,a0.z,a0.w,a1.x,a1.y,a1.z,a1.w};
      float b[8] = {b0.x,b0.y,b0.z,b0.w,b1.x,b1.y,b1.z,b1.w};
      #pragma unroll
      for (int i=0;i<8;i++)
        #pragma unroll
        for (int j=0;j<8;j++) acc[i][j] = fmaf(a[i], b[j], acc[i][j]);
    }
    __syncthreads();
  }
  if (csel < 4){
    #pragma unroll
    for (int i=0;i<8;i++){
      int r = bm + ty*8 + i;
      #pragma unroll
      for (int j=0;j<8;j+=2){
        int c = bn + tx*8 + j;
        if (c >= Hh) continue;
        float2 bv = *(const float2*)(bias + c);
        *(float2*)(C + (size_t)r*Hh + c) =
            make_float2(acc[i][j]+bv.x, acc[i][j+1]+bv.y);
      }
    }
  } else {
    #pragma unroll
    for (int i=0;i<8;i++){
      int r = bm + ty*8 + i;
      const float* xg = g_Xg + (size_t)r*Hh;
      #pragma unroll
      for (int j=0;j<8;j+=2){
        int c = bn + tx*8 + j;
        if (c >= Hh) continue;
        float2 xv = *(const float2*)(xg + c);
        *(float2*)(outp + (size_t)r*Hh + c) =
            make_float2(fmaxf(acc[i][j]+xv.x,0.f), fmaxf(acc[i][j+1]+xv.y,0.f));
      }
    }
  }
}

// ---------------------------------------------------------------------------
// Level 0 (deepest leaves): s = arm = 0 -> m_new = sigmoid(Xz[se])*tanh(Xh[se])
// ---------------------------------------------------------------------------
__global__ void k_lvl0(const int* __restrict__ sched, const int* __restrict__ srcv){
  int e  = sched[blockIdx.x];
  int se = srcv[e];
  const float* xz = g_Xz + (size_t)se*Hh;
  const float* xh = g_Xh + (size_t)se*Hh;
  float* mo = g_m + (size_t)e*Hh;
  int c = threadIdx.x*2;
  if (c < Hh){
    float2 a = *(const float2*)(xz+c), b = *(const float2*)(xh+c);
    *(float2*)(mo+c) = make_float2(sigmoidf_(a.x)*tanhf(b.x),
                                   sigmoidf_(a.y)*tanhf(b.y));
  }
}

// ---------------------------------------------------------------------------
// GEMM A big (dual, 128x64x8, 8x4 microtile): Z = S@WzB, MT = ARM@WhB
//   S[r]   = node_m[src[e]]  - (sub ? m[rev[e]]  : 0)
//   ARM[r] = node_rm[src[e]] - (sub ? rm[rev[e]] : 0)
// epilogue: m_new = (1-z)*s + z*mt  -> g_m[e]
// ---------------------------------------------------------------------------
__global__ __launch_bounds__(256) void k_gemmA_b(
    const int* __restrict__ sched, const int* __restrict__ srcv,
    const int* __restrict__ revv,
    const float* __restrict__ WzB, const float* __restrict__ WhB, int sub){
  __shared__ float Ss[8][128], Rs[8][128];
  __shared__ float Bz[8][64],  Bh[8][64];
  __shared__ int s_eid[128], s_se[128], s_rv[128];
  int bm = blockIdx.x*128, bn = blockIdx.y*64;
  int tid = threadIdx.x;
  if (tid < 128){
    int e = sched[bm + tid];
    s_eid[tid] = e; s_se[tid] = srcv[e]; s_rv[tid] = revv[e];
  }
  __syncthreads();
  int ty = tid>>4, tx = tid&15;
  float accZ[8][4] = {}, accH[8][4] = {};
  int lr = tid>>1, lk = (tid&1)*4;
  const float* nmr = g_nm  + (size_t)s_se[lr]*Hh;
  const float* nrr = g_nrm + (size_t)s_se[lr]*Hh;
  const float* mr  = g_m   + (size_t)s_rv[lr]*Hh;
  const float* rmr = g_rm  + (size_t)s_rv[lr]*Hh;
  int kr = tid>>5, ncB = (tid&31)*2;

  for (int k0=0; k0<Hh; k0+=8){
    #pragma unroll
    for (int u=0;u<4;u+=2){
      int gk = k0 + lk + u;
      float2 vm = make_float2(0.f,0.f), vr = make_float2(0.f,0.f);
      if (gk < Hh){
        vm = *(const float2*)(nmr+gk);
        vr = *(const float2*)(nrr+gk);
        if (sub){
          float2 a = *(const float2*)(mr+gk), b = *(const float2*)(rmr+gk);
          vm.x -= a.x; vm.y -= a.y; vr.x -= b.x; vr.y -= b.y;
        }
      }
      Ss[lk+u][lr] = vm.x; Ss[lk+u+1][lr] = vm.y;
      Rs[lk+u][lr] = vr.x; Rs[lk+u+1][lr] = vr.y;
    }
    {
      int gk = k0 + kr, gn = bn + ncB;
      bool ok = (gk<Hh) && (gn<Hh);
      float2 vz = ok? *(const float2*)(WzB + (size_t)gk*Hh + gn) : make_float2(0.f,0.f);
      float2 vh = ok? *(const float2*)(WhB + (size_t)gk*Hh + gn) : make_float2(0.f,0.f);
      Bz[kr][ncB] = vz.x; Bz[kr][ncB+1] = vz.y;
      Bh[kr][ncB] = vh.x; Bh[kr][ncB+1] = vh.y;
    }
    __syncthreads();
    #pragma unroll
    for (int kk=0; kk<8; kk++){
      float4 a0 = *(const float4*)&Ss[kk][ty*8];
      float4 a1 = *(const float4*)&Ss[kk][ty*8+4];
      float4 r0 = *(const float4*)&Rs[kk][ty*8];
      float4 r1 = *(const float4*)&Rs[kk][ty*8+4];
      float4 bz = *(const float4*)&Bz[kk][tx*4];
      float4 bh = *(const float4*)&Bh[kk][tx*4];
      float a[8] = {a0.x,a0.y,a0.z,a0.w,a1.x,a1.y,a1.z,a1.w};
      float w[8] = {r0.x,r0.y,r0.z,r0.w,r1.x,r1.y,r1.z,r1.w};
      float vz[4] = {bz.x,bz.y,bz.z,bz.w};
      float vh[4] = {bh.x,bh.y,bh.z,bh.w};
      #pragma unroll
      for (int i=0;i<8;i++)
        #pragma unroll
        for (int j=0;j<4;j++){
          accZ[i][j] = fmaf(a[i], vz[j], accZ[i][j]);
          accH[i][j] = fmaf(w[i], vh[j], accH[i][j]);
        }
    }
    __syncthreads();
  }
  #pragma unroll
  for (int i=0;i<8;i++){
    int r = ty*8 + i;
    int se = s_se[r], e = s_eid[r], rv = s_rv[r];
    const float* xz = g_Xz + (size_t)se*Hh;
    const float* xh = g_Xh + (size_t)se*Hh;
    const float* nm = g_nm + (size_t)se*Hh;
    const float* mrr= g_m  + (size_t)rv*Hh;
    float* mo = g_m + (size_t)e*Hh;
    #pragma unroll
    for (int j=0;j<4;j+=2){
      int c = bn + tx*4 + j;
      if (c >= Hh) continue;
      float2 xzv = *(const float2*)(xz+c), xhv = *(const float2*)(xh+c);
      float2 nmv = *(const float2*)(nm+c);
      float2 mv  = sub ? *(const float2*)(mrr+c) : make_float2(0.f,0.f);
      float z0 = sigmoidf_(accZ[i][j]   + xzv.x), mt0 = tanhf(accH[i][j]   + xhv.x);
      float z1 = sigmoidf_(accZ[i][j+1] + xzv.y), mt1 = tanhf(accH[i][j+1] + xhv.y);
      float s0 = nmv.x - mv.x, s1 = nmv.y - mv.y;
      *(float2*)(mo+c) = make_float2((1.f-z0)*s0 + z0*mt0,
                                     (1.f-z1)*s1 + z1*mt1);
    }
  }
}

// ---------------------------------------------------------------------------
// GEMM B big (128x128x8, 8x8): R = m_new @ Ur
// epilogue r=sigmoid(R+Xr[dst]); rm=r*m_new; write g_rm;
// deterministic non-atomic scatter into node_m/node_rm (sibling pairs on up).
// ---------------------------------------------------------------------------
__global__ __launch_bounds__(256) void k_gemmB_b(
    const int* __restrict__ sched, const int* __restrict__ dstv,
    const float* __restrict__ Ur, int up){
  __shared__ float As[8][128];
  __shared__ float Bs[8][128];
  __shared__ int s_eid[128], s_de[128];
  int bm = blockIdx.x*128, bn = blockIdx.y*128;
  int tid = threadIdx.x;
  if (tid < 128){
    int e = sched[bm + tid];
    s_eid[tid] = e; s_de[tid] = dstv[e];
  }
  __syncthreads();
  int ty = tid>>4, tx = tid&15;
  float acc[8][8] = {};
  int lr = tid>>1, lk = (tid&1)*4;
  const float* Ar = g_m + (size_t)s_eid[lr]*Hh;
  int kr = tid>>5, nc = (tid&31)*4;

  for (int k0=0; k0<Hh; k0+=8){
    #pragma unroll
    for (int u=0;u<4;u+=2){
      int gk = k0 + lk + u;
      float2 v = (gk<Hh)? *(const float2*)(Ar+gk) : make_float2(0.f,0.f);
      As[lk+u][lr] = v.x; As[lk+u+1][lr] = v.y;
    }
    {
      int gk = k0 + kr;
      const float* Br = Ur + (size_t)gk*Hh;
      #pragma unroll
      for (int u=0;u<4;u+=2){
        int gn = bn + nc + u;
        float2 v = (gk<Hh && gn<Hh)? *(const float2*)(Br+gn) : make_float2(0.f,0.f);
        Bs[kr][nc+u] = v.x; Bs[kr][nc+u+1] = v.y;
      }
    }
    __syncthreads();
    #pragma unroll
    for (int kk=0; kk<8; kk++){
      float4 a0 = *(const float4*)&As[kk][ty*8];
      float4 a1 = *(const float4*)&As[kk][ty*8+4];
      float4 b0 = *(const float4*)&Bs[kk][tx*8];
      float4 b1 = *(const float4*)&Bs[kk][tx*8+4];
      float a[8] = {a0.x,a0.y,a0.z,a0.w,a1.x,a1.y,a1.z,a1.w};
      float b[8] = {b0.x,b0.y,b0.z,b0.w,b1.x,b1.y,b1.z,b1.w};
      #pragma unroll
      for (int i=0;i<8;i++)
        #pragma unroll
        for (int j=0;j<8;j++) acc[i][j] = fmaf(a[i], b[j], acc[i][j]);
    }
    __syncthreads();
  }
  #pragma unroll
  for (int q=0;q<4;q++){
    int c = bn + tx*8 + 2*q;
    if (c >= Hh) continue;
    #pragma unroll
    for (int i=0;i<8;i+=2){
      int r0 = ty*8 + i, r1 = r0 + 1;
      int e0 = s_eid[r0], e1 = s_eid[r1];
      int d0 = s_de[r0],  d1 = s_de[r1];
      float2 mv0 = *(const float2*)(g_m + (size_t)e0*Hh + c);
      float2 mv1 = *(const float2*)(g_m + (size_t)e1*Hh + c);
      float2 x0  = *(const float2*)(g_Xr + (size_t)d0*Hh + c);
      float2 x1  = *(const float2*)(g_Xr + (size_t)d1*Hh + c);
      float2 rm0 = make_float2(sigmoidf_(acc[i][2*q]+x0.x)*mv0.x,
                               sigmoidf_(acc[i][2*q+1]+x0.y)*mv0.y);
      float2 rm1 = make_float2(sigmoidf_(acc[i+1][2*q]+x1.x)*mv1.x,
                               sigmoidf_(acc[i+1][2*q+1]+x1.y)*mv1.y);
      *(float2*)(g_rm + (size_t)e0*Hh + c) = rm0;
      *(float2*)(g_rm + (size_t)e1*Hh + c) = rm1;
      if (up){   // sibling pair shares dst
        size_t idx = (size_t)d0*Hh + c;
        float2 nm = *(float2*)(g_nm+idx), nr = *(float2*)(g_nrm+idx);
        nm.x += mv0.x + mv1.x;  nm.y += mv0.y + mv1.y;
        nr.x += rm0.x + rm1.x;  nr.y += rm0.y + rm1.y;
        *(float2*)(g_nm+idx) = nm; *(float2*)(g_nrm+idx) = nr;
      } else {
        size_t i0 = (size_t)d0*Hh + c, i1 = (size_t)d1*Hh + c;
        float2 a0v = *(float2*)(g_nm+i0), b0v = *(float2*)(g_nrm+i0);
        a0v.x += mv0.x; a0v.y += mv0.y; b0v.x += rm0.x; b0v.y += rm0.y;
        *(float2*)(g_nm+i0) = a0v; *(float2*)(g_nrm+i0) = b0v;
        float2 a1v = *(float2*)(g_nm+i1), b1v = *(float2*)(g_nrm+i1);
        a1v.x += mv1.x; a1v.y += mv1.y; b1v.x += rm1.x; b1v.y += rm1.y;
        *(float2*)(g_nm+i1) = a1v; *(float2*)(g_nrm+i1) = b1v;
      }
    }
  }
}

// ---------------------------------------------------------------------------
// Small-level variants (32x32x8, 2x2 microtile, 256 threads)
// ---------------------------------------------------------------------------
__global__ __launch_bounds__(256) void k_gemmA_s(
    const int* __restrict__ sched, const int* __restrict__ srcv,
    const int* __restrict__ revv,
    const float* __restrict__ WzB, const float* __restrict__ WhB, int sub){
  __shared__ float Ss[8][32], Rs[8][32], Bz[8][32], Bh[8][32];
  __shared__ int s_eid[32], s_se[32], s_rv[32];
  int bm = blockIdx.x*32, bn = blockIdx.y*32;
  int tid = threadIdx.x;
  if (tid < 32){
    int e = sched[bm + tid];
    s_eid[tid] = e; s_se[tid] = srcv[e]; s_rv[tid] = revv[e];
  }
  __syncthreads();
  int ty = tid>>4, tx = tid&15;
  float accZ[2][2] = {}, accH[2][2] = {};
  int lr = tid>>3, lk = tid&7;
  const float* nmr = g_nm  + (size_t)s_se[lr]*Hh;
  const float* nrr = g_nrm + (size_t)s_se[lr]*Hh;
  const float* mr  = g_m   + (size_t)s_rv[lr]*Hh;
  const float* rmr = g_rm  + (size_t)s_rv[lr]*Hh;
  int kr = tid>>5, cn = tid&31;

  for (int k0=0; k0<Hh; k0+=8){
    {
      int gk = k0 + lk;
      float vm = 0.f, vr = 0.f;
      if (gk < Hh){
        vm = nmr[gk]; vr = nrr[gk];
        if (sub){ vm -= mr[gk]; vr -= rmr[gk]; }
      }
      Ss[lk][lr] = vm; Rs[lk][lr] = vr;
    }
    {
      int gk = k0 + kr, gn = bn + cn;
      bool ok = (gk<Hh) && (gn<Hh);
      Bz[kr][cn] = ok? WzB[(size_t)gk*Hh + gn] : 0.f;
      Bh[kr][cn] = ok? WhB[(size_t)gk*Hh + gn] : 0.f;
    }
    __syncthreads();
    #pragma unroll
    for (int kk=0; kk<8; kk++){
      float a0=Ss[kk][ty*2], a1=Ss[kk][ty*2+1];
      float w0=Rs[kk][ty*2], w1=Rs[kk][ty*2+1];
      float z0=Bz[kk][tx*2], z1=Bz[kk][tx*2+1];
      float h0=Bh[kk][tx*2], h1=Bh[kk][tx*2+1];
      accZ[0][0]=fmaf(a0,z0,accZ[0][0]); accZ[0][1]=fmaf(a0,z1,accZ[0][1]);
      accZ[1][0]=fmaf(a1,z0,accZ[1][0]); accZ[1][1]=fmaf(a1,z1,accZ[1][1]);
      accH[0][0]=fmaf(w0,h0,accH[0][0]); accH[0][1]=fmaf(w0,h1,accH[0][1]);
      accH[1][0]=fmaf(w1,h0,accH[1][0]); accH[1][1]=fmaf(w1,h1,accH[1][1]);
    }
    __syncthreads();
  }
  #pragma unroll
  for (int i=0;i<2;i++){
    int r = ty*2 + i;
    int se = s_se[r], e = s_eid[r], rv = s_rv[r];
    #pragma unroll
    for (int j=0;j<2;j++){
      int c = bn + tx*2 + j;
      if (c >= Hh) continue;
      float z  = sigmoidf_(accZ[i][j] + g_Xz[(size_t)se*Hh + c]);
      float mt = tanhf   (accH[i][j] + g_Xh[(size_t)se*Hh + c]);
      float s  = g_nm[(size_t)se*Hh + c] - (sub ? g_m[(size_t)rv*Hh + c] : 0.f);
      g_m[(size_t)e*Hh + c] = (1.f - z)*s + z*mt;
    }
  }
}

__global__ __launch_bounds__(256) void k_gemmB_s(
    const int* __restrict__ sched, const int* __restrict__ dstv,
    const float* __restrict__ Ur, int up){
  __shared__ float As[8][32], Bs[8][32];
  __shared__ int s_eid[32], s_de[32];
  int bm = blockIdx.x*32, bn = blockIdx.y*32;
  int tid = threadIdx.x;
  if (tid < 32){
    int e = sched[bm + tid];
    s_eid[tid] = e; s_de[tid] = dstv[e];
  }
  __syncthreads();
  int ty = tid>>4, tx = tid&15;
  float acc[2][2] = {};
  int lr = tid>>3, lk = tid&7;
  const float* Ar = g_m + (size_t)s_eid[lr]*Hh;
  int kr = tid>>5, cn = tid&31;

  for (int k0=0; k0<Hh; k0+=8){
    {
      int gk = k0 + lk;
      As[lk][lr] = (gk<Hh)? Ar[gk] : 0.f;
    }
    {
      int gk = k0 + kr, gn = bn + cn;
      Bs[kr][cn] = ((gk<Hh)&&(gn<Hh))? Ur[(size_t)gk*Hh + gn] : 0.f;
    }
    __syncthreads();
    #pragma unroll
    for (int kk=0; kk<8; kk++){
      float a0=As[kk][ty*2], a1=As[kk][ty*2+1];
      float b0=Bs[kk][tx*2], b1=Bs[kk][tx*2+1];
      acc[0][0]=fmaf(a0,b0,acc[0][0]); acc[0][1]=fmaf(a0,b1,acc[0][1]);
      acc[1][0]=fmaf(a1,b0,acc[1][0]); acc[1][1]=fmaf(a1,b1,acc[1][1]);
    }
    __syncthreads();
  }
  int r0 = ty*2, r1 = ty*2+1;
  int e0 = s_eid[r0], e1 = s_eid[r1];
  int d0 = s_de[r0],  d1 = s_de[r1];
  #pragma unroll
  for (int j=0;j<2;j++){
    int c = bn + tx*2 + j;
    if (c >= Hh) continue;
    float mv0 = g_m[(size_t)e0*Hh + c];
    float mv1 = g_m[(size_t)e1*Hh + c];
    float rm0 = sigmoidf_(acc[0][j] + g_Xr[(size_t)d0*Hh + c]) * mv0;
    float rm1 = sigmoidf_(acc[1][j] + g_Xr[(size_t)d1*Hh + c]) * mv1;
    g_rm[(size_t)e0*Hh + c] = rm0;
    g_rm[(size_t)e1*Hh + c] = rm1;
    if (up){   // sibling pair shares dst
      size_t idx = (size_t)d0*Hh + c;
      g_nm[idx]  += mv0 + mv1;
      g_nrm[idx] += rm0 + rm1;
    } else {
      g_nm[(size_t)d0*Hh + c]  += mv0;
      g_nrm[(size_t)d0*Hh + c] += rm0;
      g_nm[(size_t)d1*Hh + c]  += mv1;
      g_nrm[(size_t)d1*Hh + c] += rm1;
    }
  }
}

// ---------------------------------------------------------------------------
// kernel_launch
// Inputs: 0 wid, 1 src, 2 dst, 3 rev, 4 sched, 5 emb, 6 Wz, 7 bz,
//         8 Wr, 9 Ur, 10 bur, 11 Wh, 12 bh, 13 Wg, 14 bg
// ---------------------------------------------------------------------------
extern "C" void kernel_launch(void* const* d_in, const int* in_sizes, int n_in,
                              void* d_out, int out_size) {
  const int*   wid   = (const int*)  d_in[0];
  const int*   srcv  = (const int*)  d_in[1];
  const int*   dstv  = (const int*)  d_in[2];
  const int*   revv  = (const int*)  d_in[3];
  const int*   sched = (const int*)  d_in[4];
  const float* emb   = (const float*)d_in[5];
  const float* Wz    = (const float*)d_in[6];
  const float* bz    = (const float*)d_in[7];
  const float* Wr    = (const float*)d_in[8];
  const float* Ur    = (const float*)d_in[9];
  const float* bur   = (const float*)d_in[10];
  const float* Wh    = (const float*)d_in[11];
  const float* bh    = (const float*)d_in[12];
  const float* Wg    = (const float*)d_in[13];
  const float* bg    = (const float*)d_in[14];
  float* out = (float*)d_out;

  const int lmax = in_sizes[4] / 12;   // 8192
  static const int NeTab[12] = {8192,4096,2048,1024,512,256,
                                 256,512,1024,2048,4096,8192};

  // init + precompute (hoisted x-GEMMs)
  k_init<<<(NNODE*(Hh/2) + 255)/256, 256>>>(wid, emb);
  dim3 gpre(NNODE/128, 4);
  k_gemmC<<<gpre, 256>>>(Wz, bz,  0, 0, nullptr);  // Xz
  k_gemmC<<<gpre, 256>>>(Wh, bh,  0, 1, nullptr);  // Xh
  k_gemmC<<<gpre, 256>>>(Wr, bur, 0, 2, nullptr);  // Xr
  k_gemmC<<<gpre, 256>>>(Wg, bg,  0, 3, nullptr);  // Xg

  // level 0 (s = arm = 0): pointwise m_new, then R-GEMM + scatter
  k_lvl0<<<NeTab[0], 256>>>(sched, srcv);
  {
    dim3 g(NeTab[0]/128, 4);
    k_gemmB_b<<<g, 256>>>(sched, dstv, Ur, 1);
  }
  // levels 1..11
  for (int lvl = 1; lvl < 12; lvl++) {
    int Ne  = NeTab[lvl];
    int sub = (lvl >= 6) ? 1 : 0;
    int up  = (lvl <  6) ? 1 : 0;
    const int* sc = sched + lvl*lmax;
    if (Ne >= 2048){
      dim3 gA(Ne/128, 8);
      dim3 gB(Ne/128, 4);
      k_gemmA_b<<<gA, 256>>>(sc, srcv, revv, Wz + Hh*Hh, Wh + Hh*Hh, sub);
      k_gemmB_b<<<gB, 256>>>(sc, dstv, Ur, up);
    } else {
      dim3 g(Ne/32, 15);
      k_gemmA_s<<<g, 256>>>(sc, srcv, revv, Wz + Hh*Hh, Wh + Hh*Hh, sub);
      k_gemmB_s<<<g, 256>>>(sc, dstv, Ur, up);
    }
  }

  // readout
  dim3 gf(NNODE/128, 4);
  k_gemmC<<<gf, 256>>>(Wg + Hh*Hh, nullptr, 1, 4, out);
}

// round 4
// speedup vs baseline: 1.8057x; 1.3988x over previous
#include <cuda_runtime.h>
#include <math.h>

// Problem constants (B=128 trees, depth D=6, NPT=127)
#define Hh     450
#define NNODE  16256   // 128*127
#define NEDGE  32256   // 2*128*126
#define Vv     780     // vocabulary size

// Scratch (static device globals; allocation-free kernel_launch)
__device__ float g_Tz [Vv*Hh];     // sigmoid-gate table  emb@Wz_top + bz
__device__ float g_Th [Vv*Hh];     // candidate table     emb@Wh_top + bh
__device__ float g_Tr [Vv*Hh];     // reset-gate table    emb@Wr     + bur
__device__ float g_Tg [Vv*Hh];     // readout table       emb@Wg_top + bg
__device__ float g_m  [NEDGE*Hh];
__device__ float g_rm [NEDGE*Hh];
__device__ float g_nm [NNODE*Hh];
__device__ float g_nrm[NNODE*Hh];

__device__ __forceinline__ float sigmoidf_(float v){ return 1.0f/(1.0f+expf(-v)); }

// ---------------------------------------------------------------------------
// init: zero node accumulators
// ---------------------------------------------------------------------------
__global__ void k_init(){
  int i4 = blockIdx.x*blockDim.x + threadIdx.x;
  const int N4 = NNODE*Hh/2;
  if (i4 < N4){
    ((float2*)g_nm)[i4]  = make_float2(0.f,0.f);
    ((float2*)g_nrm)[i4] = make_float2(0.f,0.f);
  }
}

// ---------------------------------------------------------------------------
// Vocab-table GEMM: T(which) = emb @ W + bias   (M=780, N=K=450)
// 128x128 tile, 8x8 microtile
// ---------------------------------------------------------------------------
__global__ __launch_bounds__(256) void k_vocab(
    const float* __restrict__ emb, const float* __restrict__ W,
    const float* __restrict__ bias, int which){
  __shared__ float As[8][128];
  __shared__ float Bs[8][128];
  float* T = (which==0)?g_Tz:(which==1)?g_Th:(which==2)?g_Tr:g_Tg;
  int bm = blockIdx.x*128, bn = blockIdx.y*128;
  int tid = threadIdx.x, ty = tid>>4, tx = tid&15;
  float acc[8][8] = {};
  int lr = tid>>1, lk = (tid&1)*4;
  int rr = bm + lr; if (rr >= Vv) rr = Vv-1;       // clamp for loads
  const float* Ar = emb + (size_t)rr*Hh;
  int kr = tid>>5, nc = (tid&31)*4;

  for (int k0=0; k0<Hh; k0+=8){
    #pragma unroll
    for (int u=0;u<4;u+=2){
      int gk = k0 + lk + u;
      float2 v = (gk<Hh)? *(const float2*)(Ar+gk) : make_float2(0.f,0.f);
      As[lk+u][lr] = v.x; As[lk+u+1][lr] = v.y;
    }
    {
      int gk = k0 + kr;
      const float* Br = W + (size_t)gk*Hh;
      #pragma unroll
      for (int u=0;u<4;u+=2){
        int gn = bn + nc + u;
        float2 v = (gk<Hh && gn<Hh)? *(const float2*)(Br+gn) : make_float2(0.f,0.f);
        Bs[kr][nc+u] = v.x; Bs[kr][nc+u+1] = v.y;
      }
    }
    __syncthreads();
    #pragma unroll
    for (int kk=0; kk<8; kk++){
      float4 a0 = *(const float4*)&As[kk][ty*8];
      float4 a1 = *(const float4*)&As[kk][ty*8+4];
      float4 b0 = *(const float4*)&Bs[kk][tx*8];
      float4 b1 = *(const float4*)&Bs[kk][tx*8+4];
      float a[8] = {a0.x,a0.y,a0.z,a0.w,a1.x,a1.y,a1.z,a1.w};
      float b[8] = {b0.x,b0.y,b0.z,b0.w,b1.x,b1.y,b1.z,b1.w};
      #pragma unroll
      for (int i=0;i<8;i++)
        #pragma unroll
        for (int j=0;j<8;j++) acc[i][j] = fmaf(a[i], b[j], acc[i][j]);
    }
    __syncthreads();
  }
  #pragma unroll
  for (int i=0;i<8;i++){
    int r = bm + ty*8 + i;
    if (r >= Vv) continue;
    #pragma unroll
    for (int j=0;j<8;j+=2){
      int c = bn + tx*8 + j;
      if (c >= Hh) continue;
      float2 bv = *(const float2*)(bias + c);
      *(float2*)(T + (size_t)r*Hh + c) =
          make_float2(acc[i][j]+bv.x, acc[i][j+1]+bv.y);
    }
  }
}

// ---------------------------------------------------------------------------
// Level 0 (deepest leaves): s = arm = 0 -> m_new = sigmoid(Tz[w])*tanh(Th[w])
// ---------------------------------------------------------------------------
__global__ void k_lvl0(const int* __restrict__ sched, const int* __restrict__ srcv,
                       const int* __restrict__ wid){
  int e  = sched[blockIdx.x];
  int w  = wid[srcv[e]];
  const float* xz = g_Tz + (size_t)w*Hh;
  const float* xh = g_Th + (size_t)w*Hh;
  float* mo = g_m + (size_t)e*Hh;
  int c = threadIdx.x*2;
  if (c < Hh){
    float2 a = *(const float2*)(xz+c), b = *(const float2*)(xh+c);
    *(float2*)(mo+c) = make_float2(sigmoidf_(a.x)*tanhf(b.x),
                                   sigmoidf_(a.y)*tanhf(b.y));
  }
}

// ---------------------------------------------------------------------------
// GEMM A big (dual, 128x64x8, 8x4 microtile, reg-prefetch pipelined):
//   Z = S@WzB, MT = ARM@WhB
//   S[r]   = node_m[src[e]]  - (sub ? m[rev[e]]  : 0)
//   ARM[r] = node_rm[src[e]] - (sub ? rm[rev[e]] : 0)
// epilogue: m_new = (1-z)*s + z*mt  -> g_m[e]
// ---------------------------------------------------------------------------
__global__ __launch_bounds__(256) void k_gemmA_b(
    const int* __restrict__ sched, const int* __restrict__ srcv,
    const int* __restrict__ revv,  const int* __restrict__ wid,
    const float* __restrict__ WzB, const float* __restrict__ WhB, int sub){
  __shared__ float Ss[8][128], Rs[8][128];
  __shared__ float Bz[8][64],  Bh[8][64];
  __shared__ int s_eid[128], s_se[128], s_rv[128], s_w[128];
  int bm = blockIdx.x*128, bn = blockIdx.y*64;
  int tid = threadIdx.x;
  if (tid < 128){
    int e = sched[bm + tid];
    int se = srcv[e];
    s_eid[tid] = e; s_se[tid] = se; s_rv[tid] = revv[e]; s_w[tid] = wid[se];
  }
  __syncthreads();
  int ty = tid>>4, tx = tid&15;
  float accZ[8][4] = {}, accH[8][4] = {};
  int lr = tid>>1, lk = (tid&1)*4;
  const float* nmr = g_nm  + (size_t)s_se[lr]*Hh;
  const float* nrr = g_nrm + (size_t)s_se[lr]*Hh;
  const float* mr  = g_m   + (size_t)s_rv[lr]*Hh;
  const float* rmr = g_rm  + (size_t)s_rv[lr]*Hh;
  int kr = tid>>5, ncB = (tid&31)*2;

  // prefetch tile k0=0
  float2 pm[2], pr[2], pz, ph;
  #pragma unroll
  for (int u=0;u<2;u++){
    int gk = lk + 2*u;
    float2 vm = make_float2(0.f,0.f), vr = make_float2(0.f,0.f);
    if (gk < Hh){
      vm = *(const float2*)(nmr+gk); vr = *(const float2*)(nrr+gk);
      if (sub){
        float2 a = *(const float2*)(mr+gk), b = *(const float2*)(rmr+gk);
        vm.x -= a.x; vm.y -= a.y; vr.x -= b.x; vr.y -= b.y;
      }
    }
    pm[u] = vm; pr[u] = vr;
  }
  {
    int gk = kr, gn = bn + ncB;
    bool ok = (gk<Hh) && (gn<Hh);
    pz = ok? *(const float2*)(WzB + (size_t)gk*Hh + gn) : make_float2(0.f,0.f);
    ph = ok? *(const float2*)(WhB + (size_t)gk*Hh + gn) : make_float2(0.f,0.f);
  }

  for (int k0=0; k0<Hh; k0+=8){
    Ss[lk  ][lr] = pm[0].x; Ss[lk+1][lr] = pm[0].y;
    Ss[lk+2][lr] = pm[1].x; Ss[lk+3][lr] = pm[1].y;
    Rs[lk  ][lr] = pr[0].x; Rs[lk+1][lr] = pr[0].y;
    Rs[lk+2][lr] = pr[1].x; Rs[lk+3][lr] = pr[1].y;
    Bz[kr][ncB] = pz.x; Bz[kr][ncB+1] = pz.y;
    Bh[kr][ncB] = ph.x; Bh[kr][ncB+1] = ph.y;
    __syncthreads();
    int kn = k0 + 8;
    if (kn < Hh){
      #pragma unroll
      for (int u=0;u<2;u++){
        int gk = kn + lk + 2*u;
        float2 vm = make_float2(0.f,0.f), vr = make_float2(0.f,0.f);
        if (gk < Hh){
          vm = *(const float2*)(nmr+gk); vr = *(const float2*)(nrr+gk);
          if (sub){
            float2 a = *(const float2*)(mr+gk), b = *(const float2*)(rmr+gk);
            vm.x -= a.x; vm.y -= a.y; vr.x -= b.x; vr.y -= b.y;
          }
        }
        pm[u] = vm; pr[u] = vr;
      }
      int gk = kn + kr, gn = bn + ncB;
      bool ok = (gk<Hh) && (gn<Hh);
      pz = ok? *(const float2*)(WzB + (size_t)gk*Hh + gn) : make_float2(0.f,0.f);
      ph = ok? *(const float2*)(WhB + (size_t)gk*Hh + gn) : make_float2(0.f,0.f);
    }
    #pragma unroll
    for (int kk=0; kk<8; kk++){
      float4 a0 = *(const float4*)&Ss[kk][ty*8];
      float4 a1 = *(const float4*)&Ss[kk][ty*8+4];
      float4 r0 = *(const float4*)&Rs[kk][ty*8];
      float4 r1 = *(const float4*)&Rs[kk][ty*8+4];
      float4 bz = *(const float4*)&Bz[kk][tx*4];
      float4 bh = *(const float4*)&Bh[kk][tx*4];
      float a[8] = {a0.x,a0.y,a0.z,a0.w,a1.x,a1.y,a1.z,a1.w};
      float w[8] = {r0.x,r0.y,r0.z,r0.w,r1.x,r1.y,r1.z,r1.w};
      float vz[4] = {bz.x,bz.y,bz.z,bz.w};
      float vh[4] = {bh.x,bh.y,bh.z,bh.w};
      #pragma unroll
      for (int i=0;i<8;i++)
        #pragma unroll
        for (int j=0;j<4;j++){
          accZ[i][j] = fmaf(a[i], vz[j], accZ[i][j]);
          accH[i][j] = fmaf(w[i], vh[j], accH[i][j]);
        }
    }
    __syncthreads();
  }
  #pragma unroll
  for (int i=0;i<8;i++){
    int r = ty*8 + i;
    int se = s_se[r], e = s_eid[r], rv = s_rv[r], w = s_w[r];
    const float* xz = g_Tz + (size_t)w*Hh;
    const float* xh = g_Th + (size_t)w*Hh;
    const float* nm = g_nm + (size_t)se*Hh;
    const float* mrr= g_m  + (size_t)rv*Hh;
    float* mo = g_m + (size_t)e*Hh;
    #pragma unroll
    for (int j=0;j<4;j+=2){
      int c = bn + tx*4 + j;
      if (c >= Hh) continue;
      float2 xzv = *(const float2*)(xz+c), xhv = *(const float2*)(xh+c);
      float2 nmv = *(const float2*)(nm+c);
      float2 mv  = sub ? *(const float2*)(mrr+c) : make_float2(0.f,0.f);
      float z0 = sigmoidf_(accZ[i][j]   + xzv.x), mt0 = tanhf(accH[i][j]   + xhv.x);
      float z1 = sigmoidf_(accZ[i][j+1] + xzv.y), mt1 = tanhf(accH[i][j+1] + xhv.y);
      float s0 = nmv.x - mv.x, s1 = nmv.y - mv.y;
      *(float2*)(mo+c) = make_float2((1.f-z0)*s0 + z0*mt0,
                                     (1.f-z1)*s1 + z1*mt1);
    }
  }
}

// ---------------------------------------------------------------------------
// GEMM B big (128x128x8, 8x8, reg-prefetch pipelined): R = m_new @ Ur
// epilogue r=sigmoid(R+Tr[wid[dst]]); rm=r*m_new; write g_rm;
// deterministic non-atomic scatter into node_m/node_rm (sibling pairs on up).
// ---------------------------------------------------------------------------
__global__ __launch_bounds__(256) void k_gemmB_b(
    const int* __restrict__ sched, const int* __restrict__ dstv,
    const int* __restrict__ wid, const float* __restrict__ Ur, int up){
  __shared__ float As[8][128];
  __shared__ float Bs[8][128];
  __shared__ int s_eid[128], s_de[128], s_wd[128];
  int bm = blockIdx.x*128, bn = blockIdx.y*128;
  int tid = threadIdx.x;
  if (tid < 128){
    int e = sched[bm + tid];
    int de = dstv[e];
    s_eid[tid] = e; s_de[tid] = de; s_wd[tid] = wid[de];
  }
  __syncthreads();
  int ty = tid>>4, tx = tid&15;
  float acc[8][8] = {};
  int lr = tid>>1, lk = (tid&1)*4;
  const float* Ar = g_m + (size_t)s_eid[lr]*Hh;
  int kr = tid>>5, nc = (tid&31)*4;

  // prefetch tile k0=0
  float2 pa[2], pb[2];
  #pragma unroll
  for (int u=0;u<2;u++){
    int gk = lk + 2*u;
    pa[u] = (gk<Hh)? *(const float2*)(Ar+gk) : make_float2(0.f,0.f);
  }
  #pragma unroll
  for (int u=0;u<2;u++){
    int gk = kr, gn = bn + nc + 2*u;
    pb[u] = (gk<Hh && gn<Hh)? *(const float2*)(Ur + (size_t)gk*Hh + gn)
                            : make_float2(0.f,0.f);
  }

  for (int k0=0; k0<Hh; k0+=8){
    As[lk  ][lr] = pa[0].x; As[lk+1][lr] = pa[0].y;
    As[lk+2][lr] = pa[1].x; As[lk+3][lr] = pa[1].y;
    Bs[kr][nc]   = pb[0].x; Bs[kr][nc+1] = pb[0].y;
    Bs[kr][nc+2] = pb[1].x; Bs[kr][nc+3] = pb[1].y;
    __syncthreads();
    int kn = k0 + 8;
    if (kn < Hh){
      #pragma unroll
      for (int u=0;u<2;u++){
        int gk = kn + lk + 2*u;
        pa[u] = (gk<Hh)? *(const float2*)(Ar+gk) : make_float2(0.f,0.f);
      }
      #pragma unroll
      for (int u=0;u<2;u++){
        int gk = kn + kr, gn = bn + nc + 2*u;
        pb[u] = (gk<Hh && gn<Hh)? *(const float2*)(Ur + (size_t)gk*Hh + gn)
                                : make_float2(0.f,0.f);
      }
    }
    #pragma unroll
    for (int kk=0; kk<8; kk++){
      float4 a0 = *(const float4*)&As[kk][ty*8];
      float4 a1 = *(const float4*)&As[kk][ty*8+4];
      float4 b0 = *(const float4*)&Bs[kk][tx*8];
      float4 b1 = *(const float4*)&Bs[kk][tx*8+4];
      float a[8] = {a0.x,a0.y,a0.z,a0.w,a1.x,a1.y,a1.z,a1.w};
      float b[8] = {b0.x,b0.y,b0.z,b0.w,b1.x,b1.y,b1.z,b1.w};
      #pragma unroll
      for (int i=0;i<8;i++)
        #pragma unroll
        for (int j=0;j<8;j++) acc[i][j] = fmaf(a[i], b[j], acc[i][j]);
    }
    __syncthreads();
  }
  #pragma unroll
  for (int q=0;q<4;q++){
    int c = bn + tx*8 + 2*q;
    if (c >= Hh) continue;
    #pragma unroll
    for (int i=0;i<8;i+=2){
      int r0 = ty*8 + i, r1 = r0 + 1;
      int e0 = s_eid[r0], e1 = s_eid[r1];
      int d0 = s_de[r0],  d1 = s_de[r1];
      int w0 = s_wd[r0],  w1 = s_wd[r1];
      float2 mv0 = *(const float2*)(g_m + (size_t)e0*Hh + c);
      float2 mv1 = *(const float2*)(g_m + (size_t)e1*Hh + c);
      float2 x0  = *(const float2*)(g_Tr + (size_t)w0*Hh + c);
      float2 x1  = *(const float2*)(g_Tr + (size_t)w1*Hh + c);
      float2 rm0 = make_float2(sigmoidf_(acc[i][2*q]+x0.x)*mv0.x,
                               sigmoidf_(acc[i][2*q+1]+x0.y)*mv0.y);
      float2 rm1 = make_float2(sigmoidf_(acc[i+1][2*q]+x1.x)*mv1.x,
                               sigmoidf_(acc[i+1][2*q+1]+x1.y)*mv1.y);
      *(float2*)(g_rm + (size_t)e0*Hh + c) = rm0;
      *(float2*)(g_rm + (size_t)e1*Hh + c) = rm1;
      if (up){   // sibling pair shares dst
        size_t idx = (size_t)d0*Hh + c;
        float2 nm = *(float2*)(g_nm+idx), nr = *(float2*)(g_nrm+idx);
        nm.x += mv0.x + mv1.x;  nm.y += mv0.y + mv1.y;
        nr.x += rm0.x + rm1.x;  nr.y += rm0.y + rm1.y;
        *(float2*)(g_nm+idx) = nm; *(float2*)(g_nrm+idx) = nr;
      } else {
        size_t i0 = (size_t)d0*Hh + c, i1 = (size_t)d1*Hh + c;
        float2 a0v = *(float2*)(g_nm+i0), b0v = *(float2*)(g_nrm+i0);
        a0v.x += mv0.x; a0v.y += mv0.y; b0v.x += rm0.x; b0v.y += rm0.y;
        *(float2*)(g_nm+i0) = a0v; *(float2*)(g_nrm+i0) = b0v;
        float2 a1v = *(float2*)(g_nm+i1), b1v = *(float2*)(g_nrm+i1);
        a1v.x += mv1.x; a1v.y += mv1.y; b1v.x += rm1.x; b1v.y += rm1.y;
        *(float2*)(g_nm+i1) = a1v; *(float2*)(g_nrm+i1) = b1v;
      }
    }
  }
}

// ---------------------------------------------------------------------------
// Small-level variants (32x32x8, 2x2 microtile, 256 threads)
// ---------------------------------------------------------------------------
__global__ __launch_bounds__(256) void k_gemmA_s(
    const int* __restrict__ sched, const int* __restrict__ srcv,
    const int* __restrict__ revv,  const int* __restrict__ wid,
    const float* __restrict__ WzB, const float* __restrict__ WhB, int sub){
  __shared__ float Ss[8][32], Rs[8][32], Bz[8][32], Bh[8][32];
  __shared__ int s_eid[32], s_se[32], s_rv[32], s_w[32];
  int bm = blockIdx.x*32, bn = blockIdx.y*32;
  int tid = threadIdx.x;
  if (tid < 32){
    int e = sched[bm + tid];
    int se = srcv[e];
    s_eid[tid] = e; s_se[tid] = se; s_rv[tid] = revv[e]; s_w[tid] = wid[se];
  }
  __syncthreads();
  int ty = tid>>4, tx = tid&15;
  float accZ[2][2] = {}, accH[2][2] = {};
  int lr = tid>>3, lk = tid&7;
  const float* nmr = g_nm  + (size_t)s_se[lr]*Hh;
  const float* nrr = g_nrm + (size_t)s_se[lr]*Hh;
  const float* mr  = g_m   + (size_t)s_rv[lr]*Hh;
  const float* rmr = g_rm  + (size_t)s_rv[lr]*Hh;
  int kr = tid>>5, cn = tid&31;

  for (int k0=0; k0<Hh; k0+=8){
    {
      int gk = k0 + lk;
      float vm = 0.f, vr = 0.f;
      if (gk < Hh){
        vm = nmr[gk]; vr = nrr[gk];
        if (sub){ vm -= mr[gk]; vr -= rmr[gk]; }
      }
      Ss[lk][lr] = vm; Rs[lk][lr] = vr;
    }
    {
      int gk = k0 + kr, gn = bn + cn;
      bool ok = (gk<Hh) && (gn<Hh);
      Bz[kr][cn] = ok? WzB[(size_t)gk*Hh + gn] : 0.f;
      Bh[kr][cn] = ok? WhB[(size_t)gk*Hh + gn] : 0.f;
    }
    __syncthreads();
    #pragma unroll
    for (int kk=0; kk<8; kk++){
      float a0=Ss[kk][ty*2], a1=Ss[kk][ty*2+1];
      float w0=Rs[kk][ty*2], w1=Rs[kk][ty*2+1];
      float z0=Bz[kk][tx*2], z1=Bz[kk][tx*2+1];
      float h0=Bh[kk][tx*2], h1=Bh[kk][tx*2+1];
      accZ[0][0]=fmaf(a0,z0,accZ[0][0]); accZ[0][1]=fmaf(a0,z1,accZ[0][1]);
      accZ[1][0]=fmaf(a1,z0,accZ[1][0]); accZ[1][1]=fmaf(a1,z1,accZ[1][1]);
      accH[0][0]=fmaf(w0,h0,accH[0][0]); accH[0][1]=fmaf(w0,h1,accH[0][1]);
      accH[1][0]=fmaf(w1,h0,accH[1][0]); accH[1][1]=fmaf(w1,h1,accH[1][1]);
    }
    __syncthreads();
  }
  #pragma unroll
  for (int i=0;i<2;i++){
    int r = ty*2 + i;
    int se = s_se[r], e = s_eid[r], rv = s_rv[r], w = s_w[r];
    #pragma unroll
    for (int j=0;j<2;j++){
      int c = bn + tx*2 + j;
      if (c >= Hh) continue;
      float z  = sigmoidf_(accZ[i][j] + g_Tz[(size_t)w*Hh + c]);
      float mt = tanhf   (accH[i][j] + g_Th[(size_t)w*Hh + c]);
      float s  = g_nm[(size_t)se*Hh + c] - (sub ? g_m[(size_t)rv*Hh + c] : 0.f);
      g_m[(size_t)e*Hh + c] = (1.f - z)*s + z*mt;
    }
  }
}

__global__ __launch_bounds__(256) void k_gemmB_s(
    const int* __restrict__ sched, const int* __restrict__ dstv,
    const int* __restrict__ wid, const float* __restrict__ Ur, int up){
  __shared__ float As[8][32], Bs[8][32];
  __shared__ int s_eid[32], s_de[32], s_wd[32];
  int bm = blockIdx.x*32, bn = blockIdx.y*32;
  int tid = threadIdx.x;
  if (tid < 32){
    int e = sched[bm + tid];
    int de = dstv[e];
    s_eid[tid] = e; s_de[tid] = de; s_wd[tid] = wid[de];
  }
  __syncthreads();
  int ty = tid>>4, tx = tid&15;
  float acc[2][2] = {};
  int lr = tid>>3, lk = tid&7;
  const float* Ar = g_m + (size_t)s_eid[lr]*Hh;
  int kr = tid>>5, cn = tid&31;

  for (int k0=0; k0<Hh; k0+=8){
    {
      int gk = k0 + lk;
      As[lk][lr] = (gk<Hh)? Ar[gk] : 0.f;
    }
    {
      int gk = k0 + kr, gn = bn + cn;
      Bs[kr][cn] = ((gk<Hh)&&(gn<Hh))? Ur[(size_t)gk*Hh + gn] : 0.f;
    }
    __syncthreads();
    #pragma unroll
    for (int kk=0; kk<8; kk++){
      float a0=As[kk][ty*2], a1=As[kk][ty*2+1];
      float b0=Bs[kk][tx*2], b1=Bs[kk][tx*2+1];
      acc[0][0]=fmaf(a0,b0,acc[0][0]); acc[0][1]=fmaf(a0,b1,acc[0][1]);
      acc[1][0]=fmaf(a1,b0,acc[1][0]); acc[1][1]=fmaf(a1,b1,acc[1][1]);
    }
    __syncthreads();
  }
  int r0 = ty*2, r1 = ty*2+1;
  int e0 = s_eid[r0], e1 = s_eid[r1];
  int d0 = s_de[r0],  d1 = s_de[r1];
  int w0 = s_wd[r0],  w1 = s_wd[r1];
  #pragma unroll
  for (int j=0;j<2;j++){
    int c = bn + tx*2 + j;
    if (c >= Hh) continue;
    float mv0 = g_m[(size_t)e0*Hh + c];
    float mv1 = g_m[(size_t)e1*Hh + c];
    float rm0 = sigmoidf_(acc[0][j] + g_Tr[(size_t)w0*Hh + c]) * mv0;
    float rm1 = sigmoidf_(acc[1][j] + g_Tr[(size_t)w1*Hh + c]) * mv1;
    g_rm[(size_t)e0*Hh + c] = rm0;
    g_rm[(size_t)e1*Hh + c] = rm1;
    if (up){   // sibling pair shares dst
      size_t idx = (size_t)d0*Hh + c;
      g_nm[idx]  += mv0 + mv1;
      g_nrm[idx] += rm0 + rm1;
    } else {
      g_nm[(size_t)d0*Hh + c]  += mv0;
      g_nrm[(size_t)d0*Hh + c] += rm0;
      g_nm[(size_t)d1*Hh + c]  += mv1;
      g_nrm[(size_t)d1*Hh + c] += rm1;
    }
  }
}

// ---------------------------------------------------------------------------
// Final readout: out = relu(Tg[wid[r]] + node_m @ WgB)   (pipelined)
// ---------------------------------------------------------------------------
__global__ __launch_bounds__(256) void k_final(
    const int* __restrict__ wid, const float* __restrict__ WgB,
    float* __restrict__ out){
  __shared__ float As[8][128];
  __shared__ float Bs[8][128];
  int bm = blockIdx.x*128, bn = blockIdx.y*128;
  int tid = threadIdx.x, ty = tid>>4, tx = tid&15;
  float acc[8][8] = {};
  int lr = tid>>1, lk = (tid&1)*4;
  const float* Ar = g_nm + (size_t)(bm+lr)*Hh;
  int kr = tid>>5, nc = (tid&31)*4;

  float2 pa[2], pb[2];
  #pragma unroll
  for (int u=0;u<2;u++){
    int gk = lk + 2*u;
    pa[u] = (gk<Hh)? *(const float2*)(Ar+gk) : make_float2(0.f,0.f);
  }
  #pragma unroll
  for (int u=0;u<2;u++){
    int gk = kr, gn = bn + nc + 2*u;
    pb[u] = (gk<Hh && gn<Hh)? *(const float2*)(WgB + (size_t)gk*Hh + gn)
                            : make_float2(0.f,0.f);
  }

  for (int k0=0; k0<Hh; k0+=8){
    As[lk  ][lr] = pa[0].x; As[lk+1][lr] = pa[0].y;
    As[lk+2][lr] = pa[1].x; As[lk+3][lr] = pa[1].y;
    Bs[kr][nc]   = pb[0].x; Bs[kr][nc+1] = pb[0].y;
    Bs[kr][nc+2] = pb[1].x; Bs[kr][nc+3] = pb[1].y;
    __syncthreads();
    int kn = k0 + 8;
    if (kn < Hh){
      #pragma unroll
      for (int u=0;u<2;u++){
        int gk = kn + lk + 2*u;
        pa[u] = (gk<Hh)? *(const float2*)(Ar+gk) : make_float2(0.f,0.f);
      }
      #pragma unroll
      for (int u=0;u<2;u++){
        int gk = kn + kr, gn = bn + nc + 2*u;
        pb[u] = (gk<Hh && gn<Hh)? *(const float2*)(WgB + (size_t)gk*Hh + gn)
                                : make_float2(0.f,0.f);
      }
    }
    #pragma unroll
    for (int kk=0; kk<8; kk++){
      float4 a0 = *(const float4*)&As[kk][ty*8];
      float4 a1 = *(const float4*)&As[kk][ty*8+4];
      float4 b0 = *(const float4*)&Bs[kk][tx*8];
      float4 b1 = *(const float4*)&Bs[kk][tx*8+4];
      float a[8] = {a0.x,a0.y,a0.z,a0.w,a1.x,a1.y,a1.z,a1.w};
      float b[8] = {b0.x,b0.y,b0.z,b0.w,b1.x,b1.y,b1.z,b1.w};
      #pragma unroll
      for (int i=0;i<8;i++)
        #pragma unroll
        for (int j=0;j<8;j++) acc[i][j] = fmaf(a[i], b[j], acc[i][j]);
    }
    __syncthreads();
  }
  #pragma unroll
  for (int i=0;i<8;i++){
    int r = bm + ty*8 + i;
    const float* xg = g_Tg + (size_t)wid[r]*Hh;
    #pragma unroll
    for (int j=0;j<8;j+=2){
      int c = bn + tx*8 + j;
      if (c >= Hh) continue;
      float2 xv = *(const float2*)(xg + c);
      *(float2*)(out + (size_t)r*Hh + c) =
          make_float2(fmaxf(acc[i][j]+xv.x,0.f), fmaxf(acc[i][j+1]+xv.y,0.f));
    }
  }
}

// ---------------------------------------------------------------------------
// kernel_launch
// Inputs: 0 wid, 1 src, 2 dst, 3 rev, 4 sched, 5 emb, 6 Wz, 7 bz,
//         8 Wr, 9 Ur, 10 bur, 11 Wh, 12 bh, 13 Wg, 14 bg
// ---------------------------------------------------------------------------
extern "C" void kernel_launch(void* const* d_in, const int* in_sizes, int n_in,
                              void* d_out, int out_size) {
  const int*   wid   = (const int*)  d_in[0];
  const int*   srcv  = (const int*)  d_in[1];
  const int*   dstv  = (const int*)  d_in[2];
  const int*   revv  = (const int*)  d_in[3];
  const int*   sched = (const int*)  d_in[4];
  const float* emb   = (const float*)d_in[5];
  const float* Wz    = (const float*)d_in[6];
  const float* bz    = (const float*)d_in[7];
  const float* Wr    = (const float*)d_in[8];
  const float* Ur    = (const float*)d_in[9];
  const float* bur   = (const float*)d_in[10];
  const float* Wh    = (const float*)d_in[11];
  const float* bh    = (const float*)d_in[12];
  const float* Wg    = (const float*)d_in[13];
  const float* bg    = (const float*)d_in[14];
  float* out = (float*)d_out;

  const int lmax = in_sizes[4] / 12;   // 8192
  static const int NeTab[12] = {8192,4096,2048,1024,512,256,
                                 256,512,1024,2048,4096,8192};

  // init + vocab tables (780 rows instead of 16256!)
  k_init<<<(NNODE*(Hh/2) + 255)/256, 256>>>();
  dim3 gv((Vv + 127)/128, 4);
  k_vocab<<<gv, 256>>>(emb, Wz,        bz,  0);  // Tz
  k_vocab<<<gv, 256>>>(emb, Wh,        bh,  1);  // Th
  k_vocab<<<gv, 256>>>(emb, Wr,        bur, 2);  // Tr
  k_vocab<<<gv, 256>>>(emb, Wg,        bg,  3);  // Tg

  // level 0 (s = arm = 0): pointwise m_new, then R-GEMM + scatter
  k_lvl0<<<NeTab[0], 256>>>(sched, srcv, wid);
  {
    dim3 g(NeTab[0]/128, 4);
    k_gemmB_b<<<g, 256>>>(sched, dstv, wid, Ur, 1);
  }
  // levels 1..11
  for (int lvl = 1; lvl < 12; lvl++) {
    int Ne  = NeTab[lvl];
    int sub = (lvl >= 6) ? 1 : 0;
    int up  = (lvl <  6) ? 1 : 0;
    const int* sc = sched + lvl*lmax;
    if (Ne >= 2048){
      dim3 gA(Ne/128, 8);
      dim3 gB(Ne/128, 4);
      k_gemmA_b<<<gA, 256>>>(sc, srcv, revv, wid, Wz + Hh*Hh, Wh + Hh*Hh, sub);
      k_gemmB_b<<<gB, 256>>>(sc, dstv, wid, Ur, up);
    } else {
      dim3 g(Ne/32, 15);
      k_gemmA_s<<<g, 256>>>(sc, srcv, revv, wid, Wz + Hh*Hh, Wh + Hh*Hh, sub);
      k_gemmB_s<<<g, 256>>>(sc, dstv, wid, Ur, up);
    }
  }

  // readout
  dim3 gf(NNODE/128, 4);
  k_final<<<gf, 256>>>(wid, Wg + Hh*Hh, out);
}

// round 5
// speedup vs baseline: 2.0311x; 1.1248x over previous
#include <cuda_runtime.h>
#include <math.h>

// Problem constants (B=128 trees, depth D=6, NPT=127)
#define Hh     450
#define NNODE  16256   // 128*127
#define NEDGE  32256   // 2*128*126
#define Vv     780     // vocabulary size

// Scratch (static device globals; allocation-free kernel_launch)
__device__ float g_Tz [Vv*Hh];     // sigmoid-gate table  emb@Wz_top + bz
__device__ float g_Th [Vv*Hh];     // candidate table     emb@Wh_top + bh
__device__ float g_Tr [Vv*Hh];     // reset-gate table    emb@Wr     + bur
__device__ float g_Tg [Vv*Hh];     // readout table       emb@Wg_top + bg
__device__ float g_m  [NEDGE*Hh];
__device__ float g_rm [NEDGE*Hh];
__device__ float g_nm [NNODE*Hh];
__device__ float g_nrm[NNODE*Hh];

__device__ __forceinline__ float sigmoidf_(float v){ return 1.0f/(1.0f+expf(-v)); }

// ---------------------------------------------------------------------------
// init: zero node accumulators
// ---------------------------------------------------------------------------
__global__ void k_init(){
  int i4 = blockIdx.x*blockDim.x + threadIdx.x;
  const int N4 = NNODE*Hh/2;
  if (i4 < N4){
    ((float2*)g_nm)[i4]  = make_float2(0.f,0.f);
    ((float2*)g_nrm)[i4] = make_float2(0.f,0.f);
  }
}

// ---------------------------------------------------------------------------
// Fused vocab-table GEMM: T[z] = emb @ W[z] + bias[z]   (M=780, N=K=450)
// blockIdx.z selects which table. 128x128 tile, 8x8 microtile.
// ---------------------------------------------------------------------------
__global__ __launch_bounds__(256) void k_vocab4(
    const float* __restrict__ emb,
    const float* __restrict__ W0, const float* __restrict__ b0,
    const float* __restrict__ W1, const float* __restrict__ b1,
    const float* __restrict__ W2, const float* __restrict__ b2,
    const float* __restrict__ W3, const float* __restrict__ b3){
  __shared__ float As[8][128];
  __shared__ float Bs[8][128];
  int which = blockIdx.z;
  const float* W    = (which==0)?W0:(which==1)?W1:(which==2)?W2:W3;
  const float* bias = (which==0)?b0:(which==1)?b1:(which==2)?b2:b3;
  float* T = (which==0)?g_Tz:(which==1)?g_Th:(which==2)?g_Tr:g_Tg;
  int bm = blockIdx.x*128, bn = blockIdx.y*128;
  int tid = threadIdx.x, ty = tid>>4, tx = tid&15;
  float acc[8][8] = {};
  int lr = tid>>1, lk = (tid&1)*4;
  int rr = bm + lr; if (rr >= Vv) rr = Vv-1;       // clamp for loads
  const float* Ar = emb + (size_t)rr*Hh;
  int kr = tid>>5, nc = (tid&31)*4;

  for (int k0=0; k0<Hh; k0+=8){
    #pragma unroll
    for (int u=0;u<4;u+=2){
      int gk = k0 + lk + u;
      float2 v = (gk<Hh)? *(const float2*)(Ar+gk) : make_float2(0.f,0.f);
      As[lk+u][lr] = v.x; As[lk+u+1][lr] = v.y;
    }
    {
      int gk = k0 + kr;
      const float* Br = W + (size_t)gk*Hh;
      #pragma unroll
      for (int u=0;u<4;u+=2){
        int gn = bn + nc + u;
        float2 v = (gk<Hh && gn<Hh)? *(const float2*)(Br+gn) : make_float2(0.f,0.f);
        Bs[kr][nc+u] = v.x; Bs[kr][nc+u+1] = v.y;
      }
    }
    __syncthreads();
    #pragma unroll
    for (int kk=0; kk<8; kk++){
      float4 a0 = *(const float4*)&As[kk][ty*8];
      float4 a1 = *(const float4*)&As[kk][ty*8+4];
      float4 b0v = *(const float4*)&Bs[kk][tx*8];
      float4 b1v = *(const float4*)&Bs[kk][tx*8+4];
      float a[8] = {a0.x,a0.y,a0.z,a0.w,a1.x,a1.y,a1.z,a1.w};
      float b[8] = {b0v.x,b0v.y,b0v.z,b0v.w,b1v.x,b1v.y,b1v.z,b1v.w};
      #pragma unroll
      for (int i=0;i<8;i++)
        #pragma unroll
        for (int j=0;j<8;j++) acc[i][j] = fmaf(a[i], b[j], acc[i][j]);
    }
    __syncthreads();
  }
  #pragma unroll
  for (int i=0;i<8;i++){
    int r = bm + ty*8 + i;
    if (r >= Vv) continue;
    #pragma unroll
    for (int j=0;j<8;j+=2){
      int c = bn + tx*8 + j;
      if (c >= Hh) continue;
      float2 bv = *(const float2*)(bias + c);
      *(float2*)(T + (size_t)r*Hh + c) =
          make_float2(acc[i][j]+bv.x, acc[i][j+1]+bv.y);
    }
  }
}

// ---------------------------------------------------------------------------
// Level 0 (deepest leaves): s = arm = 0 -> m_new = sigmoid(Tz[w])*tanh(Th[w])
// ---------------------------------------------------------------------------
__global__ void k_lvl0(const int* __restrict__ sched, const int* __restrict__ srcv,
                       const int* __restrict__ wid){
  int e  = sched[blockIdx.x];
  int w  = wid[srcv[e]];
  const float* xz = g_Tz + (size_t)w*Hh;
  const float* xh = g_Th + (size_t)w*Hh;
  float* mo = g_m + (size_t)e*Hh;
  int c = threadIdx.x*2;
  if (c < Hh){
    float2 a = *(const float2*)(xz+c), b = *(const float2*)(xh+c);
    *(float2*)(mo+c) = make_float2(sigmoidf_(a.x)*tanhf(b.x),
                                   sigmoidf_(a.y)*tanhf(b.y));
  }
}

// ---------------------------------------------------------------------------
// Level 11 scatter: rm of the last down level is never consumed ->
// skip the R GEMM entirely; just node_m[dst] += m[e]. dst unique per edge.
// ---------------------------------------------------------------------------
__global__ void k_scat11(const int* __restrict__ sched, const int* __restrict__ dstv){
  int e  = sched[blockIdx.x];
  int de = dstv[e];
  const float* mi = g_m  + (size_t)e*Hh;
  float* nm       = g_nm + (size_t)de*Hh;
  int c = threadIdx.x*2;
  if (c < Hh){
    float2 a = *(const float2*)(mi+c);
    float2 b = *(const float2*)(nm+c);
    *(float2*)(nm+c) = make_float2(a.x+b.x, a.y+b.y);
  }
}

// ---------------------------------------------------------------------------
// GEMM A big (dual, 128x64x8, 8x4 microtile, reg-prefetch pipelined):
//   Z = S@WzB, MT = ARM@WhB
// epilogue: m_new = (1-z)*s + z*mt  -> g_m[e]
// ---------------------------------------------------------------------------
__global__ __launch_bounds__(256) void k_gemmA_b(
    const int* __restrict__ sched, const int* __restrict__ srcv,
    const int* __restrict__ revv,  const int* __restrict__ wid,
    const float* __restrict__ WzB, const float* __restrict__ WhB, int sub){
  __shared__ float Ss[8][128], Rs[8][128];
  __shared__ float Bz[8][64],  Bh[8][64];
  __shared__ int s_eid[128], s_se[128], s_rv[128], s_w[128];
  int bm = blockIdx.x*128, bn = blockIdx.y*64;
  int tid = threadIdx.x;
  if (tid < 128){
    int e = sched[bm + tid];
    int se = srcv[e];
    s_eid[tid] = e; s_se[tid] = se; s_rv[tid] = revv[e]; s_w[tid] = wid[se];
  }
  __syncthreads();
  int ty = tid>>4, tx = tid&15;
  float accZ[8][4] = {}, accH[8][4] = {};
  int lr = tid>>1, lk = (tid&1)*4;
  const float* nmr = g_nm  + (size_t)s_se[lr]*Hh;
  const float* nrr = g_nrm + (size_t)s_se[lr]*Hh;
  const float* mr  = g_m   + (size_t)s_rv[lr]*Hh;
  const float* rmr = g_rm  + (size_t)s_rv[lr]*Hh;
  int kr = tid>>5, ncB = (tid&31)*2;

  float2 pm[2], pr[2], pz, ph;
  #pragma unroll
  for (int u=0;u<2;u++){
    int gk = lk + 2*u;
    float2 vm = make_float2(0.f,0.f), vr = make_float2(0.f,0.f);
    if (gk < Hh){
      vm = *(const float2*)(nmr+gk); vr = *(const float2*)(nrr+gk);
      if (sub){
        float2 a = *(const float2*)(mr+gk), b = *(const float2*)(rmr+gk);
        vm.x -= a.x; vm.y -= a.y; vr.x -= b.x; vr.y -= b.y;
      }
    }
    pm[u] = vm; pr[u] = vr;
  }
  {
    int gk = kr, gn = bn + ncB;
    bool ok = (gk<Hh) && (gn<Hh);
    pz = ok? *(const float2*)(WzB + (size_t)gk*Hh + gn) : make_float2(0.f,0.f);
    ph = ok? *(const float2*)(WhB + (size_t)gk*Hh + gn) : make_float2(0.f,0.f);
  }

  for (int k0=0; k0<Hh; k0+=8){
    Ss[lk  ][lr] = pm[0].x; Ss[lk+1][lr] = pm[0].y;
    Ss[lk+2][lr] = pm[1].x; Ss[lk+3][lr] = pm[1].y;
    Rs[lk  ][lr] = pr[0].x; Rs[lk+1][lr] = pr[0].y;
    Rs[lk+2][lr] = pr[1].x; Rs[lk+3][lr] = pr[1].y;
    Bz[kr][ncB] = pz.x; Bz[kr][ncB+1] = pz.y;
    Bh[kr][ncB] = ph.x; Bh[kr][ncB+1] = ph.y;
    __syncthreads();
    int kn = k0 + 8;
    if (kn < Hh){
      #pragma unroll
      for (int u=0;u<2;u++){
        int gk = kn + lk + 2*u;
        float2 vm = make_float2(0.f,0.f), vr = make_float2(0.f,0.f);
        if (gk < Hh){
          vm = *(const float2*)(nmr+gk); vr = *(const float2*)(nrr+gk);
          if (sub){
            float2 a = *(const float2*)(mr+gk), b = *(const float2*)(rmr+gk);
            vm.x -= a.x; vm.y -= a.y; vr.x -= b.x; vr.y -= b.y;
          }
        }
        pm[u] = vm; pr[u] = vr;
      }
      int gk = kn + kr, gn = bn + ncB;
      bool ok = (gk<Hh) && (gn<Hh);
      pz = ok? *(const float2*)(WzB + (size_t)gk*Hh + gn) : make_float2(0.f,0.f);
      ph = ok? *(const float2*)(WhB + (size_t)gk*Hh + gn) : make_float2(0.f,0.f);
    }
    #pragma unroll
    for (int kk=0; kk<8; kk++){
      float4 a0 = *(const float4*)&Ss[kk][ty*8];
      float4 a1 = *(const float4*)&Ss[kk][ty*8+4];
      float4 r0 = *(const float4*)&Rs[kk][ty*8];
      float4 r1 = *(const float4*)&Rs[kk][ty*8+4];
      float4 bz = *(const float4*)&Bz[kk][tx*4];
      float4 bh = *(const float4*)&Bh[kk][tx*4];
      float a[8] = {a0.x,a0.y,a0.z,a0.w,a1.x,a1.y,a1.z,a1.w};
      float w[8] = {r0.x,r0.y,r0.z,r0.w,r1.x,r1.y,r1.z,r1.w};
      float vz[4] = {bz.x,bz.y,bz.z,bz.w};
      float vh[4] = {bh.x,bh.y,bh.z,bh.w};
      #pragma unroll
      for (int i=0;i<8;i++)
        #pragma unroll
        for (int j=0;j<4;j++){
          accZ[i][j] = fmaf(a[i], vz[j], accZ[i][j]);
          accH[i][j] = fmaf(w[i], vh[j], accH[i][j]);
        }
    }
    __syncthreads();
  }
  #pragma unroll
  for (int i=0;i<8;i++){
    int r = ty*8 + i;
    int se = s_se[r], e = s_eid[r], rv = s_rv[r], w = s_w[r];
    const float* xz = g_Tz + (size_t)w*Hh;
    const float* xh = g_Th + (size_t)w*Hh;
    const float* nm = g_nm + (size_t)se*Hh;
    const float* mrr= g_m  + (size_t)rv*Hh;
    float* mo = g_m + (size_t)e*Hh;
    #pragma unroll
    for (int j=0;j<4;j+=2){
      int c = bn + tx*4 + j;
      if (c >= Hh) continue;
      float2 xzv = *(const float2*)(xz+c), xhv = *(const float2*)(xh+c);
      float2 nmv = *(const float2*)(nm+c);
      float2 mv  = sub ? *(const float2*)(mrr+c) : make_float2(0.f,0.f);
      float z0 = sigmoidf_(accZ[i][j]   + xzv.x), mt0 = tanhf(accH[i][j]   + xhv.x);
      float z1 = sigmoidf_(accZ[i][j+1] + xzv.y), mt1 = tanhf(accH[i][j+1] + xhv.y);
      float s0 = nmv.x - mv.x, s1 = nmv.y - mv.y;
      *(float2*)(mo+c) = make_float2((1.f-z0)*s0 + z0*mt0,
                                     (1.f-z1)*s1 + z1*mt1);
    }
  }
}

// ---------------------------------------------------------------------------
// GEMM B big (128x128x16, 8x8, reg-prefetch pipelined): R = m_new @ Ur
// epilogue r=sigmoid(R+Tr[wid[dst]]); rm=r*m_new; write g_rm;
// deterministic non-atomic scatter into node_m/node_rm (sibling pairs on up).
// ---------------------------------------------------------------------------
__global__ __launch_bounds__(256) void k_gemmB_b(
    const int* __restrict__ sched, const int* __restrict__ dstv,
    const int* __restrict__ wid, const float* __restrict__ Ur, int up){
  __shared__ float As[16][128];
  __shared__ float Bs[16][128];
  __shared__ int s_eid[128], s_de[128], s_wd[128];
  int bm = blockIdx.x*128, bn = blockIdx.y*128;
  int tid = threadIdx.x;
  if (tid < 128){
    int e = sched[bm + tid];
    int de = dstv[e];
    s_eid[tid] = e; s_de[tid] = de; s_wd[tid] = wid[de];
  }
  __syncthreads();
  int ty = tid>>4, tx = tid&15;
  float acc[8][8] = {};
  int lr = tid>>1, lk = (tid&1)*8;      // 8 k-floats per thread
  const float* Ar = g_m + (size_t)s_eid[lr]*Hh;
  int kr = tid>>4, nc = (tid&15)*8;     // B: row 0..15, 8 cols

  float2 pa[4], pb[4];
  #pragma unroll
  for (int u=0;u<4;u++){
    int gk = lk + 2*u;
    pa[u] = (gk<Hh)? *(const float2*)(Ar+gk) : make_float2(0.f,0.f);
  }
  #pragma unroll
  for (int u=0;u<4;u++){
    int gk = kr, gn = bn + nc + 2*u;
    pb[u] = (gk<Hh && gn<Hh)? *(const float2*)(Ur + (size_t)gk*Hh + gn)
                            : make_float2(0.f,0.f);
  }

  for (int k0=0; k0<Hh; k0+=16){
    #pragma unroll
    for (int u=0;u<4;u++){
      As[lk+2*u  ][lr] = pa[u].x; As[lk+2*u+1][lr] = pa[u].y;
      Bs[kr][nc+2*u] = pb[u].x;   Bs[kr][nc+2*u+1] = pb[u].y;
    }
    __syncthreads();
    int kn = k0 + 16;
    if (kn < Hh){
      #pragma unroll
      for (int u=0;u<4;u++){
        int gk = kn + lk + 2*u;
        pa[u] = (gk<Hh)? *(const float2*)(Ar+gk) : make_float2(0.f,0.f);
      }
      #pragma unroll
      for (int u=0;u<4;u++){
        int gk = kn + kr, gn = bn + nc + 2*u;
        pb[u] = (gk<Hh && gn<Hh)? *(const float2*)(Ur + (size_t)gk*Hh + gn)
                                : make_float2(0.f,0.f);
      }
    }
    #pragma unroll
    for (int kk=0; kk<16; kk++){
      float4 a0 = *(const float4*)&As[kk][ty*8];
      float4 a1 = *(const float4*)&As[kk][ty*8+4];
      float4 b0 = *(const float4*)&Bs[kk][tx*8];
      float4 b1 = *(const float4*)&Bs[kk][tx*8+4];
      float a[8] = {a0.x,a0.y,a0.z,a0.w,a1.x,a1.y,a1.z,a1.w};
      float b[8] = {b0.x,b0.y,b0.z,b0.w,b1.x,b1.y,b1.z,b1.w};
      #pragma unroll
      for (int i=0;i<8;i++)
        #pragma unroll
        for (int j=0;j<8;j++) acc[i][j] = fmaf(a[i], b[j], acc[i][j]);
    }
    __syncthreads();
  }
  #pragma unroll
  for (int q=0;q<4;q++){
    int c = bn + tx*8 + 2*q;
    if (c >= Hh) continue;
    #pragma unroll
    for (int i=0;i<8;i+=2){
      int r0 = ty*8 + i, r1 = r0 + 1;
      int e0 = s_eid[r0], e1 = s_eid[r1];
      int d0 = s_de[r0],  d1 = s_de[r1];
      int w0 = s_wd[r0],  w1 = s_wd[r1];
      float2 mv0 = *(const float2*)(g_m + (size_t)e0*Hh + c);
      float2 mv1 = *(const float2*)(g_m + (size_t)e1*Hh + c);
      float2 x0  = *(const float2*)(g_Tr + (size_t)w0*Hh + c);
      float2 x1  = *(const float2*)(g_Tr + (size_t)w1*Hh + c);
      float2 rm0 = make_float2(sigmoidf_(acc[i][2*q]+x0.x)*mv0.x,
                               sigmoidf_(acc[i][2*q+1]+x0.y)*mv0.y);
      float2 rm1 = make_float2(sigmoidf_(acc[i+1][2*q]+x1.x)*mv1.x,
                               sigmoidf_(acc[i+1][2*q+1]+x1.y)*mv1.y);
      *(float2*)(g_rm + (size_t)e0*Hh + c) = rm0;
      *(float2*)(g_rm + (size_t)e1*Hh + c) = rm1;
      if (up){   // sibling pair shares dst
        size_t idx = (size_t)d0*Hh + c;
        float2 nm = *(float2*)(g_nm+idx), nr = *(float2*)(g_nrm+idx);
        nm.x += mv0.x + mv1.x;  nm.y += mv0.y + mv1.y;
        nr.x += rm0.x + rm1.x;  nr.y += rm0.y + rm1.y;
        *(float2*)(g_nm+idx) = nm; *(float2*)(g_nrm+idx) = nr;
      } else {
        size_t i0 = (size_t)d0*Hh + c, i1 = (size_t)d1*Hh + c;
        float2 a0v = *(float2*)(g_nm+i0), b0v = *(float2*)(g_nrm+i0);
        a0v.x += mv0.x; a0v.y += mv0.y; b0v.x += rm0.x; b0v.y += rm0.y;
        *(float2*)(g_nm+i0) = a0v; *(float2*)(g_nrm+i0) = b0v;
        float2 a1v = *(float2*)(g_nm+i1), b1v = *(float2*)(g_nrm+i1);
        a1v.x += mv1.x; a1v.y += mv1.y; b1v.x += rm1.x; b1v.y += rm1.y;
        *(float2*)(g_nm+i1) = a1v; *(float2*)(g_nrm+i1) = b1v;
      }
    }
  }
}

// ---------------------------------------------------------------------------
// Small-level variants (32x32x8, 2x2 microtile, 256 threads)
// ---------------------------------------------------------------------------
__global__ __launch_bounds__(256) void k_gemmA_s(
    const int* __restrict__ sched, const int* __restrict__ srcv,
    const int* __restrict__ revv,  const int* __restrict__ wid,
    const float* __restrict__ WzB, const float* __restrict__ WhB, int sub){
  __shared__ float Ss[8][32], Rs[8][32], Bz[8][32], Bh[8][32];
  __shared__ int s_eid[32], s_se[32], s_rv[32], s_w[32];
  int bm = blockIdx.x*32, bn = blockIdx.y*32;
  int tid = threadIdx.x;
  if (tid < 32){
    int e = sched[bm + tid];
    int se = srcv[e];
    s_eid[tid] = e; s_se[tid] = se; s_rv[tid] = revv[e]; s_w[tid] = wid[se];
  }
  __syncthreads();
  int ty = tid>>4, tx = tid&15;
  float accZ[2][2] = {}, accH[2][2] = {};
  int lr = tid>>3, lk = tid&7;
  const float* nmr = g_nm  + (size_t)s_se[lr]*Hh;
  const float* nrr = g_nrm + (size_t)s_se[lr]*Hh;
  const float* mr  = g_m   + (size_t)s_rv[lr]*Hh;
  const float* rmr = g_rm  + (size_t)s_rv[lr]*Hh;
  int kr = tid>>5, cn = tid&31;

  for (int k0=0; k0<Hh; k0+=8){
    {
      int gk = k0 + lk;
      float vm = 0.f, vr = 0.f;
      if (gk < Hh){
        vm = nmr[gk]; vr = nrr[gk];
        if (sub){ vm -= mr[gk]; vr -= rmr[gk]; }
      }
      Ss[lk][lr] = vm; Rs[lk][lr] = vr;
    }
    {
      int gk = k0 + kr, gn = bn + cn;
      bool ok = (gk<Hh) && (gn<Hh);
      Bz[kr][cn] = ok? WzB[(size_t)gk*Hh + gn] : 0.f;
      Bh[kr][cn] = ok? WhB[(size_t)gk*Hh + gn] : 0.f;
    }
    __syncthreads();
    #pragma unroll
    for (int kk=0; kk<8; kk++){
      float a0=Ss[kk][ty*2], a1=Ss[kk][ty*2+1];
      float w0=Rs[kk][ty*2], w1=Rs[kk][ty*2+1];
      float z0=Bz[kk][tx*2], z1=Bz[kk][tx*2+1];
      float h0=Bh[kk][tx*2], h1=Bh[kk][tx*2+1];
      accZ[0][0]=fmaf(a0,z0,accZ[0][0]); accZ[0][1]=fmaf(a0,z1,accZ[0][1]);
      accZ[1][0]=fmaf(a1,z0,accZ[1][0]); accZ[1][1]=fmaf(a1,z1,accZ[1][1]);
      accH[0][0]=fmaf(w0,h0,accH[0][0]); accH[0][1]=fmaf(w0,h1,accH[0][1]);
      accH[1][0]=fmaf(w1,h0,accH[1][0]); accH[1][1]=fmaf(w1,h1,accH[1][1]);
    }
    __syncthreads();
  }
  #pragma unroll
  for (int i=0;i<2;i++){
    int r = ty*2 + i;
    int se = s_se[r], e = s_eid[r], rv = s_rv[r], w = s_w[r];
    #pragma unroll
    for (int j=0;j<2;j++){
      int c = bn + tx*2 + j;
      if (c >= Hh) continue;
      float z  = sigmoidf_(accZ[i][j] + g_Tz[(size_t)w*Hh + c]);
      float mt = tanhf   (accH[i][j] + g_Th[(size_t)w*Hh + c]);
      float s  = g_nm[(size_t)se*Hh + c] - (sub ? g_m[(size_t)rv*Hh + c] : 0.f);
      g_m[(size_t)e*Hh + c] = (1.f - z)*s + z*mt;
    }
  }
}

__global__ __launch_bounds__(256) void k_gemmB_s(
    const int* __restrict__ sched, const int* __restrict__ dstv,
    const int* __restrict__ wid, const float* __restrict__ Ur, int up){
  __shared__ float As[8][32], Bs[8][32];
  __shared__ int s_eid[32], s_de[32], s_wd[32];
  int bm = blockIdx.x*32, bn = blockIdx.y*32;
  int tid = threadIdx.x;
  if (tid < 32){
    int e = sched[bm + tid];
    int de = dstv[e];
    s_eid[tid] = e; s_de[tid] = de; s_wd[tid] = wid[de];
  }
  __syncthreads();
  int ty = tid>>4, tx = tid&15;
  float acc[2][2] = {};
  int lr = tid>>3, lk = tid&7;
  const float* Ar = g_m + (size_t)s_eid[lr]*Hh;
  int kr = tid>>5, cn = tid&31;

  for (int k0=0; k0<Hh; k0+=8){
    {
      int gk = k0 + lk;
      As[lk][lr] = (gk<Hh)? Ar[gk] : 0.f;
    }
    {
      int gk = k0 + kr, gn = bn + cn;
      Bs[kr][cn] = ((gk<Hh)&&(gn<Hh))? Ur[(size_t)gk*Hh + gn] : 0.f;
    }
    __syncthreads();
    #pragma unroll
    for (int kk=0; kk<8; kk++){
      float a0=As[kk][ty*2], a1=As[kk][ty*2+1];
      float b0=Bs[kk][tx*2], b1=Bs[kk][tx*2+1];
      acc[0][0]=fmaf(a0,b0,acc[0][0]); acc[0][1]=fmaf(a0,b1,acc[0][1]);
      acc[1][0]=fmaf(a1,b0,acc[1][0]); acc[1][1]=fmaf(a1,b1,acc[1][1]);
    }
    __syncthreads();
  }
  int r0 = ty*2, r1 = ty*2+1;
  int e0 = s_eid[r0], e1 = s_eid[r1];
  int d0 = s_de[r0],  d1 = s_de[r1];
  int w0 = s_wd[r0],  w1 = s_wd[r1];
  #pragma unroll
  for (int j=0;j<2;j++){
    int c = bn + tx*2 + j;
    if (c >= Hh) continue;
    float mv0 = g_m[(size_t)e0*Hh + c];
    float mv1 = g_m[(size_t)e1*Hh + c];
    float rm0 = sigmoidf_(acc[0][j] + g_Tr[(size_t)w0*Hh + c]) * mv0;
    float rm1 = sigmoidf_(acc[1][j] + g_Tr[(size_t)w1*Hh + c]) * mv1;
    g_rm[(size_t)e0*Hh + c] = rm0;
    g_rm[(size_t)e1*Hh + c] = rm1;
    if (up){   // sibling pair shares dst
      size_t idx = (size_t)d0*Hh + c;
      g_nm[idx]  += mv0 + mv1;
      g_nrm[idx] += rm0 + rm1;
    } else {
      g_nm[(size_t)d0*Hh + c]  += mv0;
      g_nrm[(size_t)d0*Hh + c] += rm0;
      g_nm[(size_t)d1*Hh + c]  += mv1;
      g_nrm[(size_t)d1*Hh + c] += rm1;
    }
  }
}

// ---------------------------------------------------------------------------
// Final readout: out = relu(Tg[wid[r]] + node_m @ WgB)  (128x128x16 pipelined)
// ---------------------------------------------------------------------------
__global__ __launch_bounds__(256) void k_final(
    const int* __restrict__ wid, const float* __restrict__ WgB,
    float* __restrict__ out){
  __shared__ float As[16][128];
  __shared__ float Bs[16][128];
  int bm = blockIdx.x*128, bn = blockIdx.y*128;
  int tid = threadIdx.x, ty = tid>>4, tx = tid&15;
  float acc[8][8] = {};
  int lr = tid>>1, lk = (tid&1)*8;
  const float* Ar = g_nm + (size_t)(bm+lr)*Hh;
  int kr = tid>>4, nc = (tid&15)*8;

  float2 pa[4], pb[4];
  #pragma unroll
  for (int u=0;u<4;u++){
    int gk = lk + 2*u;
    pa[u] = (gk<Hh)? *(const float2*)(Ar+gk) : make_float2(0.f,0.f);
  }
  #pragma unroll
  for (int u=0;u<4;u++){
    int gk = kr, gn = bn + nc + 2*u;
    pb[u] = (gk<Hh && gn<Hh)? *(const float2*)(WgB + (size_t)gk*Hh + gn)
                            : make_float2(0.f,0.f);
  }

  for (int k0=0; k0<Hh; k0+=16){
    #pragma unroll
    for (int u=0;u<4;u++){
      As[lk+2*u  ][lr] = pa[u].x; As[lk+2*u+1][lr] = pa[u].y;
      Bs[kr][nc+2*u] = pb[u].x;   Bs[kr][nc+2*u+1] = pb[u].y;
    }
    __syncthreads();
    int kn = k0 + 16;
    if (kn < Hh){
      #pragma unroll
      for (int u=0;u<4;u++){
        int gk = kn + lk + 2*u;
        pa[u] = (gk<Hh)? *(const float2*)(Ar+gk) : make_float2(0.f,0.f);
      }
      #pragma unroll
      for (int u=0;u<4;u++){
        int gk = kn + kr, gn = bn + nc + 2*u;
        pb[u] = (gk<Hh && gn<Hh)? *(const float2*)(WgB + (size_t)gk*Hh + gn)
                                : make_float2(0.f,0.f);
      }
    }
    #pragma unroll
    for (int kk=0; kk<16; kk++){
      float4 a0 = *(const float4*)&As[kk][ty*8];
      float4 a1 = *(const float4*)&As[kk][ty*8+4];
      float4 b0 = *(const float4*)&Bs[kk][tx*8];
      float4 b1 = *(const float4*)&Bs[kk][tx*8+4];
      float a[8] = {a0.x,a0.y,a0.z,a0.w,a1.x,a1.y,a1.z,a1.w};
      float b[8] = {b0.x,b0.y,b0.z,b0.w,b1.x,b1.y,b1.z,b1.w};
      #pragma unroll
      for (int i=0;i<8;i++)
        #pragma unroll
        for (int j=0;j<8;j++) acc[i][j] = fmaf(a[i], b[j], acc[i][j]);
    }
    __syncthreads();
  }
  #pragma unroll
  for (int i=0;i<8;i++){
    int r = bm + ty*8 + i;
    const float* xg = g_Tg + (size_t)wid[r]*Hh;
    #pragma unroll
    for (int j=0;j<8;j+=2){
      int c = bn + tx*8 + j;
      if (c >= Hh) continue;
      float2 xv = *(const float2*)(xg + c);
      *(float2*)(out + (size_t)r*Hh + c) =
          make_float2(fmaxf(acc[i][j]+xv.x,0.f), fmaxf(acc[i][j+1]+xv.y,0.f));
    }
  }
}

// ---------------------------------------------------------------------------
// kernel_launch
// Inputs: 0 wid, 1 src, 2 dst, 3 rev, 4 sched, 5 emb, 6 Wz, 7 bz,
//         8 Wr, 9 Ur, 10 bur, 11 Wh, 12 bh, 13 Wg, 14 bg
// ---------------------------------------------------------------------------
extern "C" void kernel_launch(void* const* d_in, const int* in_sizes, int n_in,
                              void* d_out, int out_size) {
  const int*   wid   = (const int*)  d_in[0];
  const int*   srcv  = (const int*)  d_in[1];
  const int*   dstv  = (const int*)  d_in[2];
  const int*   revv  = (const int*)  d_in[3];
  const int*   sched = (const int*)  d_in[4];
  const float* emb   = (const float*)d_in[5];
  const float* Wz    = (const float*)d_in[6];
  const float* bz    = (const float*)d_in[7];
  const float* Wr    = (const float*)d_in[8];
  const float* Ur    = (const float*)d_in[9];
  const float* bur   = (const float*)d_in[10];
  const float* Wh    = (const float*)d_in[11];
  const float* bh    = (const float*)d_in[12];
  const float* Wg    = (const float*)d_in[13];
  const float* bg    = (const float*)d_in[14];
  float* out = (float*)d_out;

  const int lmax = in_sizes[4] / 12;   // 8192
  static const int NeTab[12] = {8192,4096,2048,1024,512,256,
                                 256,512,1024,2048,4096,8192};

  // init + fused vocab tables (one launch, blockIdx.z selects table)
  k_init<<<(NNODE*(Hh/2) + 255)/256, 256>>>();
  dim3 gv((Vv + 127)/128, 4, 4);
  k_vocab4<<<gv, 256>>>(emb, Wz, bz, Wh, bh, Wr, bur, Wg, bg);

  // level 0 (s = arm = 0): pointwise m_new, then R-GEMM + scatter
  k_lvl0<<<NeTab[0], 256>>>(sched, srcv, wid);
  {
    dim3 g(NeTab[0]/128, 4);
    k_gemmB_b<<<g, 256>>>(sched, dstv, wid, Ur, 1);
  }
  // levels 1..10
  for (int lvl = 1; lvl < 11; lvl++) {
    int Ne  = NeTab[lvl];
    int sub = (lvl >= 6) ? 1 : 0;
    int up  = (lvl <  6) ? 1 : 0;
    const int* sc = sched + lvl*lmax;
    if (Ne >= 2048){
      dim3 gA(Ne/128, 8);
      dim3 gB(Ne/128, 4);
      k_gemmA_b<<<gA, 256>>>(sc, srcv, revv, wid, Wz + Hh*Hh, Wh + Hh*Hh, sub);
      k_gemmB_b<<<gB, 256>>>(sc, dstv, wid, Ur, up);
    } else {
      dim3 g(Ne/32, 15);
      k_gemmA_s<<<g, 256>>>(sc, srcv, revv, wid, Wz + Hh*Hh, Wh + Hh*Hh, sub);
      k_gemmB_s<<<g, 256>>>(sc, dstv, wid, Ur, up);
    }
  }
  // level 11: m_new GEMM + scatter only (rm of last down level is never read)
  {
    const int* sc = sched + 11*lmax;
    dim3 gA(NeTab[11]/128, 8);
    k_gemmA_b<<<gA, 256>>>(sc, srcv, revv, wid, Wz + Hh*Hh, Wh + Hh*Hh, 1);
    k_scat11<<<NeTab[11], 256>>>(sc, dstv);
  }

  // readout
  dim3 gf(NNODE/128, 4);
  k_final<<<gf, 256>>>(wid, Wg + Hh*Hh, out);
}